// round 1
// baseline (speedup 1.0000x reference)
#include <cuda_runtime.h>
#include <math.h>

#define BATCH 4
#define CH 64
#define OC 64
#define HH 128
#define WW 128
#define HW (HH*WW)
#define PIX (BATCH*HW)
#define K2 9
#define KKD 576            // K2*CH
#define TP 32              // pixels per deform block
#define WCHUNK 96
#define NCHUNK 6
#define SXROW (WW*65)      // padded row stride in floats (8320)

// -------- device scratch (no allocations allowed) --------
__device__ float g_xn[PIX*CH];        // x in NHWC: [b][h][w][c]
__device__ float g_offs[PIX*18];      // offsets: [pix][18]
__device__ float g_wT[KKD*OC];        // deform weights: [kk=k*64+c][o]
__device__ float g_wor[K2*CH*20];     // offset-conv weights: [k][c][p padded to 20]

// ============ kernel 1: NCHW -> NHWC transpose ============
__global__ void k_transpose(const float* __restrict__ x) {
    __shared__ float tile[32][33];
    int bh = blockIdx.z;                 // b*128 + h
    int c0 = blockIdx.y * 32;
    int w0 = blockIdx.x * 32;
    int b = bh >> 7, h = bh & 127;
    int tx = threadIdx.x, ty = threadIdx.y;
#pragma unroll
    for (int i = 0; i < 4; i++) {
        int c = c0 + ty + i*8;
        tile[ty + i*8][tx] = x[((b*CH + c)*HH + h)*WW + w0 + tx];
    }
    __syncthreads();
#pragma unroll
    for (int i = 0; i < 4; i++) {
        int w = w0 + ty + i*8;
        g_xn[(bh*WW + w)*CH + c0 + tx] = tile[tx][ty + i*8];
    }
}

// ============ kernel 2: weight reorder ============
__global__ void k_reorder(const float* __restrict__ w_off, const float* __restrict__ w_dcn) {
    int t = blockIdx.x*blockDim.x + threadIdx.x;
    int stride = gridDim.x*blockDim.x;
    for (int idx = t; idx < KKD*OC; idx += stride) {
        int kk = idx >> 6, o = idx & 63;
        int k = kk >> 6, c = kk & 63;
        g_wT[idx] = w_dcn[o*KKD + c*K2 + k];
    }
    for (int idx = t; idx < K2*CH*20; idx += stride) {
        int row = idx / 20, p = idx - row*20;
        int k = row >> 6, c = row & 63;
        g_wor[idx] = (p < 18) ? w_off[p*KKD + c*K2 + k] : 0.f;
    }
}

// ============ kernel 3: offset conv (C=64 -> 18, 3x3, pad1) ============
// Block: 256 threads = 2 output rows x 128 pixels. Stages 4 input rows + weights in smem.
__global__ void k_offconv(const float* __restrict__ b_off) {
    extern __shared__ float sm[];
    float* sx = sm;                     // 4 * SXROW floats
    float* sw = sm + 4*SXROW;           // 11520 floats
    int blk = blockIdx.x;               // b*64 + h2
    int b = blk >> 6, h2 = blk & 63;
    int t = threadIdx.x;                // 256

    for (int i = t; i < K2*CH*20; i += 256) sw[i] = g_wor[i];

    int ybase = 2*h2 - 1;               // rows ybase .. ybase+3 staged
#pragma unroll
    for (int r = 0; r < 4; r++) {
        int y = ybase + r;
        bool vy = (y >= 0) && (y < HH);
        const float* src = &g_xn[((size_t)(b*HH + y))*WW*CH];
        for (int i = t; i < WW*CH; i += 256) {
            int w = i >> 6, c = i & 63;
            sx[r*SXROW + w*65 + c] = vy ? src[i] : 0.f;
        }
    }
    __syncthreads();

    int rsel = t >> 7;                  // 0 or 1: which output row
    int w = t & 127;
    float acc[18];
#pragma unroll
    for (int p = 0; p < 18; p++) acc[p] = b_off[p];

#pragma unroll
    for (int ky = 0; ky < 3; ky++) {
#pragma unroll
        for (int kx = 0; kx < 3; kx++) {
            int xx = w + kx - 1;
            if (xx < 0 || xx >= WW) continue;
            const float* xr = &sx[(rsel + ky)*SXROW + xx*65];
            const float* wb = &sw[(ky*3 + kx)*CH*20];
            for (int c = 0; c < CH; c++) {
                float xv = xr[c];
                const float* wp = wb + c*20;
                float4 a0 = *(const float4*)(wp + 0);
                float4 a1 = *(const float4*)(wp + 4);
                float4 a2 = *(const float4*)(wp + 8);
                float4 a3 = *(const float4*)(wp + 12);
                float2 a4 = *(const float2*)(wp + 16);
                acc[0]  = fmaf(xv, a0.x, acc[0]);
                acc[1]  = fmaf(xv, a0.y, acc[1]);
                acc[2]  = fmaf(xv, a0.z, acc[2]);
                acc[3]  = fmaf(xv, a0.w, acc[3]);
                acc[4]  = fmaf(xv, a1.x, acc[4]);
                acc[5]  = fmaf(xv, a1.y, acc[5]);
                acc[6]  = fmaf(xv, a1.z, acc[6]);
                acc[7]  = fmaf(xv, a1.w, acc[7]);
                acc[8]  = fmaf(xv, a2.x, acc[8]);
                acc[9]  = fmaf(xv, a2.y, acc[9]);
                acc[10] = fmaf(xv, a2.z, acc[10]);
                acc[11] = fmaf(xv, a2.w, acc[11]);
                acc[12] = fmaf(xv, a3.x, acc[12]);
                acc[13] = fmaf(xv, a3.y, acc[13]);
                acc[14] = fmaf(xv, a3.z, acc[14]);
                acc[15] = fmaf(xv, a3.w, acc[15]);
                acc[16] = fmaf(xv, a4.x, acc[16]);
                acc[17] = fmaf(xv, a4.y, acc[17]);
            }
        }
    }
    int h = 2*h2 + rsel;
    float* dst = &g_offs[((size_t)((b*HH + h)*WW + w))*18];
#pragma unroll
    for (int p = 0; p < 18; p++) dst[p] = acc[p];
}

// ============ kernel 4: deformable conv (bilinear im2col + GEMM) ============
// Block: 256 threads, 32 pixels. Phase 1: 8 warps gather val[576][33] (kk-major).
// Phase 2: thread (p = t&31, og = t>>5) computes 8 output channels for its pixel.
__global__ void k_deform(const float* __restrict__ b_dcn, float* __restrict__ out) {
    extern __shared__ float sm[];
    float* val = sm;                    // KKD*33 = 19008 floats
    float* wsh = sm + KKD*33;           // WCHUNK*OC = 6144 floats
    int t = threadIdx.x;
    int lane = t & 31, warp = t >> 5;
    int pix0 = blockIdx.x * TP;

    // ---- phase 1: bilinear gather into im2col tile ----
    for (int task = warp; task < TP*K2; task += 8) {
        int p = task / 9;
        int k = task - p*9;
        int pix = pix0 + p;
        int b = pix >> 14;
        int hw = pix & (HW-1);
        int h = hw >> 7, w = hw & 127;
        float dy = g_offs[pix*18 + 2*k];
        float dx = g_offs[pix*18 + 2*k + 1];
        int ky = k / 3, kx = k - ky*3;
        float py = (float)(h + ky - 1) + dy;
        float px = (float)(w + kx - 1) + dx;
        float y0f = floorf(py), x0f = floorf(px);
        float wy = py - y0f, wx = px - x0f;
        int y0 = (int)y0f, x0 = (int)x0f;
        bool vy0 = (y0 >= 0) && (y0 < HH);
        bool vy1 = (y0 >= -1) && (y0 < HH-1);
        bool vx0 = (x0 >= 0) && (x0 < WW);
        bool vx1 = (x0 >= -1) && (x0 < WW-1);
        const float* base = &g_xn[(size_t)b * (HW*CH)];
        int c2 = lane*2;
        float2 v00 = make_float2(0.f,0.f), v01 = v00, v10 = v00, v11 = v00;
        if (vy0 && vx0) v00 = *(const float2*)&base[((y0  )*WW + x0    )*CH + c2];
        if (vy0 && vx1) v01 = *(const float2*)&base[((y0  )*WW + x0 + 1)*CH + c2];
        if (vy1 && vx0) v10 = *(const float2*)&base[((y0+1)*WW + x0    )*CH + c2];
        if (vy1 && vx1) v11 = *(const float2*)&base[((y0+1)*WW + x0 + 1)*CH + c2];
        float w00 = (1.f-wy)*(1.f-wx), w01 = (1.f-wy)*wx;
        float w10 = wy*(1.f-wx),       w11 = wy*wx;
        float r0 = w00*v00.x + w01*v01.x + w10*v10.x + w11*v11.x;
        float r1 = w00*v00.y + w01*v01.y + w10*v10.y + w11*v11.y;
        int kk = k*64 + c2;
        val[kk*33 + p]     = r0;
        val[(kk+1)*33 + p] = r1;
    }
    __syncthreads();

    // ---- phase 2: GEMM 32 x 64 x 576 with chunked smem weights ----
    int p = t & 31;
    int og = t >> 5;
    int ob = og * 8;
    float acc[8];
#pragma unroll
    for (int i = 0; i < 8; i++) acc[i] = 0.f;

    for (int ch = 0; ch < NCHUNK; ch++) {
        if (ch) __syncthreads();        // protect wsh overwrite
        const float4* src4 = (const float4*)&g_wT[ch*WCHUNK*OC];
        float4* dst4 = (float4*)wsh;
        for (int i = t; i < WCHUNK*OC/4; i += 256) dst4[i] = src4[i];
        __syncthreads();
        int kb = ch*WCHUNK;
#pragma unroll 4
        for (int j = 0; j < WCHUNK; j++) {
            float v = val[(kb + j)*33 + p];
            float4 wa = *(const float4*)&wsh[j*OC + ob];
            float4 wb = *(const float4*)&wsh[j*OC + ob + 4];
            acc[0] = fmaf(v, wa.x, acc[0]);
            acc[1] = fmaf(v, wa.y, acc[1]);
            acc[2] = fmaf(v, wa.z, acc[2]);
            acc[3] = fmaf(v, wa.w, acc[3]);
            acc[4] = fmaf(v, wb.x, acc[4]);
            acc[5] = fmaf(v, wb.y, acc[5]);
            acc[6] = fmaf(v, wb.z, acc[6]);
            acc[7] = fmaf(v, wb.w, acc[7]);
        }
    }

    int pix = pix0 + p;
    int b = pix >> 14;
    int hw = pix & (HW-1);
    int h = hw >> 7, w = hw & 127;
#pragma unroll
    for (int i = 0; i < 8; i++)
        out[(((size_t)(b*OC + ob + i))*HH + h)*WW + w] = acc[i] + b_dcn[ob + i];
}

// ============ launch ============
extern "C" void kernel_launch(void* const* d_in, const int* in_sizes, int n_in,
                              void* d_out, int out_size) {
    const float* x     = (const float*)d_in[0];
    const float* w_off = (const float*)d_in[1];
    const float* b_off = (const float*)d_in[2];
    const float* w_dcn = (const float*)d_in[3];
    const float* b_dcn = (const float*)d_in[4];
    float* out = (float*)d_out;

    const int SMEM_OFF = (4*SXROW + K2*CH*20) * 4;         // 179200 B
    const int SMEM_DEF = (KKD*33 + WCHUNK*OC) * 4;         // 100608 B
    cudaFuncSetAttribute(k_offconv, cudaFuncAttributeMaxDynamicSharedMemorySize, SMEM_OFF);
    cudaFuncSetAttribute(k_deform,  cudaFuncAttributeMaxDynamicSharedMemorySize, SMEM_DEF);

    k_transpose<<<dim3(WW/32, CH/32, BATCH*HH), dim3(32,8)>>>(x);
    k_reorder<<<64, 256>>>(w_off, w_dcn);
    k_offconv<<<BATCH*HH/2, 256, SMEM_OFF>>>(b_off);
    k_deform<<<PIX/TP, 256, SMEM_DEF>>>(b_dcn, out);
}

// round 2
// speedup vs baseline: 1.3227x; 1.3227x over previous
#include <cuda_runtime.h>
#include <math.h>

#define BATCH 4
#define CH 64
#define OC 64
#define HH 128
#define WW 128
#define HW (HH*WW)
#define PIX (BATCH*HW)
#define K2 9
#define KKD 576            // K2*CH
#define SXROW (WW*65)      // padded row stride in floats (8320)
#define VP 129             // val row stride (odd => conflict-free)

// -------- device scratch (no allocations allowed) --------
__device__ float g_xn[PIX*CH];        // x in NHWC: [b][h][w][c]
__device__ float g_offs[PIX*18];      // offsets: [pix][18]
__device__ float g_wT[KKD*OC];        // deform weights: [kk=k*64+c][o]
__device__ float g_wor[K2*CH*20];     // offset-conv weights: [k][c][p padded to 20]

// ============ kernel 1: NCHW -> NHWC transpose ============
__global__ void k_transpose(const float* __restrict__ x) {
    __shared__ float tile[32][33];
    int bh = blockIdx.z;                 // b*128 + h
    int c0 = blockIdx.y * 32;
    int w0 = blockIdx.x * 32;
    int b = bh >> 7, h = bh & 127;
    int tx = threadIdx.x, ty = threadIdx.y;
#pragma unroll
    for (int i = 0; i < 4; i++) {
        int c = c0 + ty + i*8;
        tile[ty + i*8][tx] = x[((b*CH + c)*HH + h)*WW + w0 + tx];
    }
    __syncthreads();
#pragma unroll
    for (int i = 0; i < 4; i++) {
        int w = w0 + ty + i*8;
        g_xn[(bh*WW + w)*CH + c0 + tx] = tile[tx][ty + i*8];
    }
}

// ============ kernel 2: weight reorder ============
__global__ void k_reorder(const float* __restrict__ w_off, const float* __restrict__ w_dcn) {
    int t = blockIdx.x*blockDim.x + threadIdx.x;
    int stride = gridDim.x*blockDim.x;
    for (int idx = t; idx < KKD*OC; idx += stride) {
        int kk = idx >> 6, o = idx & 63;
        int k = kk >> 6, c = kk & 63;
        g_wT[idx] = w_dcn[o*KKD + c*K2 + k];
    }
    for (int idx = t; idx < K2*CH*20; idx += stride) {
        int row = idx / 20, p = idx - row*20;
        int k = row >> 6, c = row & 63;
        g_wor[idx] = (p < 18) ? w_off[p*KKD + c*K2 + k] : 0.f;
    }
}

// ============ kernel 3: offset conv (C=64 -> 18, 3x3, pad1) ============
__global__ void k_offconv(const float* __restrict__ b_off) {
    extern __shared__ float sm[];
    float* sx = sm;                     // 4 * SXROW floats
    float* sw = sm + 4*SXROW;           // 11520 floats
    int blk = blockIdx.x;               // b*64 + h2
    int b = blk >> 6, h2 = blk & 63;
    int t = threadIdx.x;                // 256

    for (int i = t; i < K2*CH*20; i += 256) sw[i] = g_wor[i];

    int ybase = 2*h2 - 1;               // rows ybase .. ybase+3 staged
#pragma unroll
    for (int r = 0; r < 4; r++) {
        int y = ybase + r;
        bool vy = (y >= 0) && (y < HH);
        const float* src = &g_xn[((size_t)(b*HH + y))*WW*CH];
        for (int i = t; i < WW*CH; i += 256) {
            int w = i >> 6, c = i & 63;
            sx[r*SXROW + w*65 + c] = vy ? src[i] : 0.f;
        }
    }
    __syncthreads();

    int rsel = t >> 7;                  // 0 or 1: which output row
    int w = t & 127;
    float acc[18];
#pragma unroll
    for (int p = 0; p < 18; p++) acc[p] = b_off[p];

#pragma unroll
    for (int ky = 0; ky < 3; ky++) {
#pragma unroll
        for (int kx = 0; kx < 3; kx++) {
            int xx = w + kx - 1;
            if (xx < 0 || xx >= WW) continue;
            const float* xr = &sx[(rsel + ky)*SXROW + xx*65];
            const float* wb = &sw[(ky*3 + kx)*CH*20];
            for (int c = 0; c < CH; c++) {
                float xv = xr[c];
                const float* wp = wb + c*20;
                float4 a0 = *(const float4*)(wp + 0);
                float4 a1 = *(const float4*)(wp + 4);
                float4 a2 = *(const float4*)(wp + 8);
                float4 a3 = *(const float4*)(wp + 12);
                float2 a4 = *(const float2*)(wp + 16);
                acc[0]  = fmaf(xv, a0.x, acc[0]);
                acc[1]  = fmaf(xv, a0.y, acc[1]);
                acc[2]  = fmaf(xv, a0.z, acc[2]);
                acc[3]  = fmaf(xv, a0.w, acc[3]);
                acc[4]  = fmaf(xv, a1.x, acc[4]);
                acc[5]  = fmaf(xv, a1.y, acc[5]);
                acc[6]  = fmaf(xv, a1.z, acc[6]);
                acc[7]  = fmaf(xv, a1.w, acc[7]);
                acc[8]  = fmaf(xv, a2.x, acc[8]);
                acc[9]  = fmaf(xv, a2.y, acc[9]);
                acc[10] = fmaf(xv, a2.z, acc[10]);
                acc[11] = fmaf(xv, a2.w, acc[11]);
                acc[12] = fmaf(xv, a3.x, acc[12]);
                acc[13] = fmaf(xv, a3.y, acc[13]);
                acc[14] = fmaf(xv, a3.z, acc[14]);
                acc[15] = fmaf(xv, a3.w, acc[15]);
                acc[16] = fmaf(xv, a4.x, acc[16]);
                acc[17] = fmaf(xv, a4.y, acc[17]);
            }
        }
    }
    int h = 2*h2 + rsel;
    float* dst = &g_offs[((size_t)((b*HH + h)*WW + w))*18];
#pragma unroll
    for (int p = 0; p < 18; p++) dst[p] = acc[p];
}

// ============ kernel 4: deformable conv v2 ============
// Block: 256 threads = 8 warps, 128 pixels (one image row), 64 output channels.
// Loop over 9 kernel positions: gather val[64c][VP] chunk + stage 16KB weights,
// then register-tiled GEMM: thread = (lane -> 4 px interleaved, warp -> 8 oc).
// 6 LDS per 32 FFMA, all shared accesses conflict-free.
__global__ void __launch_bounds__(256)
k_deform(const float* __restrict__ b_dcn, float* __restrict__ out) {
    extern __shared__ float sm[];
    float* val = sm;                    // 64 * VP = 8256 floats
    float* wsh = sm + 64*VP;            // 64*64 = 4096 floats
    int t = threadIdx.x;
    int lane = t & 31, warp = t >> 5;   // warp in [0,8)
    int blk = blockIdx.x;               // b*128 + h
    int b = blk >> 7, h = blk & 127;
    int pix0 = blk * WW;
    const float* xb = &g_xn[(size_t)b * (HW*CH)];

    float acc[4][8];
#pragma unroll
    for (int i = 0; i < 4; i++)
#pragma unroll
        for (int j = 0; j < 8; j++) acc[i][j] = 0.f;

    for (int k = 0; k < K2; k++) {
        __syncthreads();                // previous GEMM done with val/wsh

        // stage weights for this kernel position: 64c x 64o (contiguous in g_wT)
        {
            const float4* src4 = (const float4*)&g_wT[k*64*OC];
            float4* dst4 = (float4*)wsh;
            dst4[t]       = src4[t];
            dst4[t + 256] = src4[t + 256];
            dst4[t + 512] = src4[t + 512];
            dst4[t + 768] = src4[t + 768];
        }

        // gather: each warp handles 16 pixels; lane = channel (l and l+32)
        int ky = k / 3, kx = k - ky*3;
#pragma unroll 2
        for (int j = 0; j < 16; j++) {
            int p = warp*16 + j;
            int pix = pix0 + p;
            float dy = g_offs[pix*18 + 2*k];
            float dx = g_offs[pix*18 + 2*k + 1];
            float py = (float)(h + ky - 1) + dy;
            float px = (float)(p + kx - 1) + dx;
            float y0f = floorf(py), x0f = floorf(px);
            float wy = py - y0f, wx = px - x0f;
            int y0 = (int)y0f, x0 = (int)x0f;
            bool vy0 = (y0 >= 0) && (y0 < HH);
            bool vy1 = (y0 >= -1) && (y0 < HH-1);
            bool vx0 = (x0 >= 0) && (x0 < WW);
            bool vx1 = (x0 >= -1) && (x0 < WW-1);
            int a00 = ((y0  )*WW + x0    )*CH + lane;
            int a01 = ((y0  )*WW + x0 + 1)*CH + lane;
            int a10 = ((y0+1)*WW + x0    )*CH + lane;
            int a11 = ((y0+1)*WW + x0 + 1)*CH + lane;
            float v00a=0.f,v01a=0.f,v10a=0.f,v11a=0.f;
            float v00b=0.f,v01b=0.f,v10b=0.f,v11b=0.f;
            if (vy0 && vx0) { v00a = xb[a00]; v00b = xb[a00+32]; }
            if (vy0 && vx1) { v01a = xb[a01]; v01b = xb[a01+32]; }
            if (vy1 && vx0) { v10a = xb[a10]; v10b = xb[a10+32]; }
            if (vy1 && vx1) { v11a = xb[a11]; v11b = xb[a11+32]; }
            float w00 = (1.f-wy)*(1.f-wx), w01 = (1.f-wy)*wx;
            float w10 = wy*(1.f-wx),       w11 = wy*wx;
            val[lane*VP + p]      = w00*v00a + w01*v01a + w10*v10a + w11*v11a;
            val[(lane+32)*VP + p] = w00*v00b + w01*v01b + w10*v10b + w11*v11b;
        }
        __syncthreads();

        // GEMM accumulate: 64 channels
        const float* wrow = &wsh[warp*8];
#pragma unroll 2
        for (int c = 0; c < CH; c++) {
            float v0 = val[c*VP + lane];
            float v1 = val[c*VP + lane + 32];
            float v2 = val[c*VP + lane + 64];
            float v3 = val[c*VP + lane + 96];
            float4 wa = *(const float4*)&wrow[c*OC];
            float4 wb = *(const float4*)&wrow[c*OC + 4];
            acc[0][0] = fmaf(v0, wa.x, acc[0][0]);
            acc[0][1] = fmaf(v0, wa.y, acc[0][1]);
            acc[0][2] = fmaf(v0, wa.z, acc[0][2]);
            acc[0][3] = fmaf(v0, wa.w, acc[0][3]);
            acc[0][4] = fmaf(v0, wb.x, acc[0][4]);
            acc[0][5] = fmaf(v0, wb.y, acc[0][5]);
            acc[0][6] = fmaf(v0, wb.z, acc[0][6]);
            acc[0][7] = fmaf(v0, wb.w, acc[0][7]);
            acc[1][0] = fmaf(v1, wa.x, acc[1][0]);
            acc[1][1] = fmaf(v1, wa.y, acc[1][1]);
            acc[1][2] = fmaf(v1, wa.z, acc[1][2]);
            acc[1][3] = fmaf(v1, wa.w, acc[1][3]);
            acc[1][4] = fmaf(v1, wb.x, acc[1][4]);
            acc[1][5] = fmaf(v1, wb.y, acc[1][5]);
            acc[1][6] = fmaf(v1, wb.z, acc[1][6]);
            acc[1][7] = fmaf(v1, wb.w, acc[1][7]);
            acc[2][0] = fmaf(v2, wa.x, acc[2][0]);
            acc[2][1] = fmaf(v2, wa.y, acc[2][1]);
            acc[2][2] = fmaf(v2, wa.z, acc[2][2]);
            acc[2][3] = fmaf(v2, wa.w, acc[2][3]);
            acc[2][4] = fmaf(v2, wb.x, acc[2][4]);
            acc[2][5] = fmaf(v2, wb.y, acc[2][5]);
            acc[2][6] = fmaf(v2, wb.z, acc[2][6]);
            acc[2][7] = fmaf(v2, wb.w, acc[2][7]);
            acc[3][0] = fmaf(v3, wa.x, acc[3][0]);
            acc[3][1] = fmaf(v3, wa.y, acc[3][1]);
            acc[3][2] = fmaf(v3, wa.z, acc[3][2]);
            acc[3][3] = fmaf(v3, wa.w, acc[3][3]);
            acc[3][4] = fmaf(v3, wb.x, acc[3][4]);
            acc[3][5] = fmaf(v3, wb.y, acc[3][5]);
            acc[3][6] = fmaf(v3, wb.z, acc[3][6]);
            acc[3][7] = fmaf(v3, wb.w, acc[3][7]);
        }
    }

    // epilogue: out is NCHW; lanes write consecutive w -> coalesced
    int ob = warp*8;
#pragma unroll
    for (int j = 0; j < 8; j++) {
        float bias = b_dcn[ob + j];
        float* dst = &out[(((size_t)(b*OC + ob + j))*HH + h)*WW];
#pragma unroll
        for (int i = 0; i < 4; i++)
            dst[lane + 32*i] = acc[i][j] + bias;
    }
}

// ============ launch ============
extern "C" void kernel_launch(void* const* d_in, const int* in_sizes, int n_in,
                              void* d_out, int out_size) {
    const float* x     = (const float*)d_in[0];
    const float* w_off = (const float*)d_in[1];
    const float* b_off = (const float*)d_in[2];
    const float* w_dcn = (const float*)d_in[3];
    const float* b_dcn = (const float*)d_in[4];
    float* out = (float*)d_out;

    const int SMEM_OFF = (4*SXROW + K2*CH*20) * 4;         // 179200 B
    const int SMEM_DEF = (64*VP + 64*OC) * 4;              // 49408 B
    cudaFuncSetAttribute(k_offconv, cudaFuncAttributeMaxDynamicSharedMemorySize, SMEM_OFF);
    cudaFuncSetAttribute(k_deform,  cudaFuncAttributeMaxDynamicSharedMemorySize, SMEM_DEF);

    k_transpose<<<dim3(WW/32, CH/32, BATCH*HH), dim3(32,8)>>>(x);
    k_reorder<<<64, 256>>>(w_off, w_dcn);
    k_offconv<<<BATCH*HH/2, 256, SMEM_OFF>>>(b_off);
    k_deform<<<BATCH*HH, 256, SMEM_DEF>>>(b_dcn, out);
}

// round 3
// speedup vs baseline: 1.3719x; 1.0372x over previous
#include <cuda_runtime.h>
#include <math.h>

#define BATCH 4
#define CH 64
#define OC 64
#define HH 128
#define WW 128
#define HW (HH*WW)
#define PIX (BATCH*HW)
#define K2 9
#define KKD 576            // K2*CH
#define SXROW (WW*65)      // padded row stride in floats (8320)
#define VP 129             // val row stride (odd => conflict-free)

// -------- device scratch (no allocations allowed) --------
__device__ float g_xn[PIX*CH];        // x in NHWC: [b][h][w][c]
__device__ float g_offs[PIX*18];      // offsets: [pix][18]
__device__ float g_wT[KKD*OC];        // deform weights: [kk=k*64+c][o]
__device__ float g_wor[K2*CH*20];     // offset-conv weights: [k][c][p padded to 20]

// ---- packed f32x2 helpers (SASS FFMA2 — only reachable via PTX) ----
__device__ __forceinline__ void ffma2(unsigned long long &acc, unsigned long long a, unsigned long long b) {
    asm("fma.rn.f32x2 %0, %1, %2, %0;" : "+l"(acc) : "l"(a), "l"(b));
}
__device__ __forceinline__ unsigned long long dup2(float v) {
    unsigned long long r;
    asm("mov.b64 %0, {%1, %1};" : "=l"(r) : "f"(v));
    return r;
}
__device__ __forceinline__ unsigned long long pack2(float a, float b) {
    unsigned long long r;
    asm("mov.b64 %0, {%1, %2};" : "=l"(r) : "f"(a), "f"(b));
    return r;
}
__device__ __forceinline__ float2 unpack2(unsigned long long a) {
    float2 r;
    asm("mov.b64 {%0, %1}, %2;" : "=f"(r.x), "=f"(r.y) : "l"(a));
    return r;
}

// ============ kernel 1: NCHW -> NHWC transpose ============
__global__ void k_transpose(const float* __restrict__ x) {
    __shared__ float tile[32][33];
    int bh = blockIdx.z;                 // b*128 + h
    int c0 = blockIdx.y * 32;
    int w0 = blockIdx.x * 32;
    int b = bh >> 7, h = bh & 127;
    int tx = threadIdx.x, ty = threadIdx.y;
#pragma unroll
    for (int i = 0; i < 4; i++) {
        int c = c0 + ty + i*8;
        tile[ty + i*8][tx] = x[((b*CH + c)*HH + h)*WW + w0 + tx];
    }
    __syncthreads();
#pragma unroll
    for (int i = 0; i < 4; i++) {
        int w = w0 + ty + i*8;
        g_xn[(bh*WW + w)*CH + c0 + tx] = tile[tx][ty + i*8];
    }
}

// ============ kernel 2: weight reorder ============
__global__ void k_reorder(const float* __restrict__ w_off, const float* __restrict__ w_dcn) {
    int t = blockIdx.x*blockDim.x + threadIdx.x;
    int stride = gridDim.x*blockDim.x;
    for (int idx = t; idx < KKD*OC; idx += stride) {
        int kk = idx >> 6, o = idx & 63;
        int k = kk >> 6, c = kk & 63;
        g_wT[idx] = w_dcn[o*KKD + c*K2 + k];
    }
    for (int idx = t; idx < K2*CH*20; idx += stride) {
        int row = idx / 20, p = idx - row*20;
        int k = row >> 6, c = row & 63;
        g_wor[idx] = (p < 18) ? w_off[p*KKD + c*K2 + k] : 0.f;
    }
}

// ============ kernel 3: offset conv (C=64 -> 18, 3x3, pad1), f32x2 ============
__global__ void k_offconv(const float* __restrict__ b_off) {
    extern __shared__ float sm[];
    float* sx = sm;                     // 4 * SXROW floats
    float* sw = sm + 4*SXROW;           // 11520 floats
    int blk = blockIdx.x;               // b*64 + h2
    int b = blk >> 6, h2 = blk & 63;
    int t = threadIdx.x;                // 256

    for (int i = t; i < K2*CH*20; i += 256) sw[i] = g_wor[i];

    int ybase = 2*h2 - 1;               // rows ybase .. ybase+3 staged
#pragma unroll
    for (int r = 0; r < 4; r++) {
        int y = ybase + r;
        bool vy = (y >= 0) && (y < HH);
        const float* src = &g_xn[((size_t)(b*HH + y))*WW*CH];
        for (int i = t; i < WW*CH; i += 256) {
            int w = i >> 6, c = i & 63;
            sx[r*SXROW + w*65 + c] = vy ? src[i] : 0.f;
        }
    }
    __syncthreads();

    int rsel = t >> 7;                  // 0 or 1: which output row
    int w = t & 127;
    unsigned long long acc[9];
#pragma unroll
    for (int p = 0; p < 9; p++) acc[p] = pack2(b_off[2*p], b_off[2*p+1]);

#pragma unroll
    for (int ky = 0; ky < 3; ky++) {
#pragma unroll
        for (int kx = 0; kx < 3; kx++) {
            int xx = w + kx - 1;
            if (xx < 0 || xx >= WW) continue;
            const float* xr = &sx[(rsel + ky)*SXROW + xx*65];
            const float* wb = &sw[(ky*3 + kx)*CH*20];
            for (int c = 0; c < CH; c++) {
                unsigned long long xv = dup2(xr[c]);
                const float* wp = wb + c*20;
                ulonglong2 p01 = *(const ulonglong2*)(wp + 0);   // pairs (0,1),(2,3)
                ulonglong2 p23 = *(const ulonglong2*)(wp + 4);   // (4,5),(6,7)
                ulonglong2 p45 = *(const ulonglong2*)(wp + 8);   // (8,9),(10,11)
                ulonglong2 p67 = *(const ulonglong2*)(wp + 12);  // (12,13),(14,15)
                unsigned long long p8 = *(const unsigned long long*)(wp + 16); // (16,17)
                ffma2(acc[0], xv, p01.x);
                ffma2(acc[1], xv, p01.y);
                ffma2(acc[2], xv, p23.x);
                ffma2(acc[3], xv, p23.y);
                ffma2(acc[4], xv, p45.x);
                ffma2(acc[5], xv, p45.y);
                ffma2(acc[6], xv, p67.x);
                ffma2(acc[7], xv, p67.y);
                ffma2(acc[8], xv, p8);
            }
        }
    }
    int h = 2*h2 + rsel;
    float* dst = &g_offs[((size_t)((b*HH + h)*WW + w))*18];
#pragma unroll
    for (int p = 0; p < 9; p++) {
        float2 r = unpack2(acc[p]);
        dst[2*p]   = r.x;
        dst[2*p+1] = r.y;
    }
}

// ============ kernel 4: deformable conv v3 (f32x2 GEMM) ============
// Block: 256 threads = 8 warps, 128 pixels (one image row), 64 output channels.
// Per kernel position: gather val[64c][VP] + stage 16KB weights, then
// register-tiled f32x2 GEMM: thread = (lane -> 4 px interleaved, warp -> 8 oc
// as 4 packed pairs). 16 FFMA2 + 4 dup + 6 LDS per channel.
__global__ void __launch_bounds__(256)
k_deform(const float* __restrict__ b_dcn, float* __restrict__ out) {
    extern __shared__ float sm[];
    float* val = sm;                    // 64 * VP = 8256 floats
    float* wsh = sm + 64*VP;            // 64*64 = 4096 floats
    int t = threadIdx.x;
    int lane = t & 31, warp = t >> 5;   // warp in [0,8)
    int blk = blockIdx.x;               // b*128 + h
    int b = blk >> 7, h = blk & 127;
    int pix0 = blk * WW;
    const float* xb = &g_xn[(size_t)b * (HW*CH)];

    unsigned long long acc[4][4];
#pragma unroll
    for (int i = 0; i < 4; i++)
#pragma unroll
        for (int j = 0; j < 4; j++) acc[i][j] = 0ull;

    for (int k = 0; k < K2; k++) {
        __syncthreads();                // previous GEMM done with val/wsh

        // stage weights for this kernel position: 64c x 64o (contiguous in g_wT)
        {
            const float4* src4 = (const float4*)&g_wT[k*64*OC];
            float4* dst4 = (float4*)wsh;
            dst4[t]       = src4[t];
            dst4[t + 256] = src4[t + 256];
            dst4[t + 512] = src4[t + 512];
            dst4[t + 768] = src4[t + 768];
        }

        // gather: each warp handles 16 pixels; lane covers channels 2l,2l+1
        int ky = k / 3, kx = k - ky*3;
        int c2 = lane*2;
#pragma unroll 2
        for (int j = 0; j < 16; j++) {
            int p = warp*16 + j;
            int pix = pix0 + p;
            float dy = g_offs[pix*18 + 2*k];
            float dx = g_offs[pix*18 + 2*k + 1];
            float py = (float)(h + ky - 1) + dy;
            float px = (float)(p + kx - 1) + dx;
            float y0f = floorf(py), x0f = floorf(px);
            float wy = py - y0f, wx = px - x0f;
            int y0 = (int)y0f, x0 = (int)x0f;
            bool vy0 = (y0 >= 0) && (y0 < HH);
            bool vy1 = (y0 >= -1) && (y0 < HH-1);
            bool vx0 = (x0 >= 0) && (x0 < WW);
            bool vx1 = (x0 >= -1) && (x0 < WW-1);
            int a00 = ((y0  )*WW + x0    )*CH + c2;
            int a01 = ((y0  )*WW + x0 + 1)*CH + c2;
            int a10 = ((y0+1)*WW + x0    )*CH + c2;
            int a11 = ((y0+1)*WW + x0 + 1)*CH + c2;
            float2 v00 = make_float2(0.f,0.f), v01 = v00, v10 = v00, v11 = v00;
            if (vy0 && vx0) v00 = *(const float2*)&xb[a00];
            if (vy0 && vx1) v01 = *(const float2*)&xb[a01];
            if (vy1 && vx0) v10 = *(const float2*)&xb[a10];
            if (vy1 && vx1) v11 = *(const float2*)&xb[a11];
            float w00 = (1.f-wy)*(1.f-wx), w01 = (1.f-wy)*wx;
            float w10 = wy*(1.f-wx),       w11 = wy*wx;
            val[c2*VP + p]     = w00*v00.x + w01*v01.x + w10*v10.x + w11*v11.x;
            val[(c2+1)*VP + p] = w00*v00.y + w01*v01.y + w10*v10.y + w11*v11.y;
        }
        __syncthreads();

        // GEMM accumulate: 64 channels, f32x2 packed over oc pairs
        const float* wrow = &wsh[warp*8];
#pragma unroll 2
        for (int c = 0; c < CH; c++) {
            unsigned long long vd0 = dup2(val[c*VP + lane]);
            unsigned long long vd1 = dup2(val[c*VP + lane + 32]);
            unsigned long long vd2 = dup2(val[c*VP + lane + 64]);
            unsigned long long vd3 = dup2(val[c*VP + lane + 96]);
            ulonglong2 wa = *(const ulonglong2*)&wrow[c*OC];     // (w0,w1),(w2,w3)
            ulonglong2 wb = *(const ulonglong2*)&wrow[c*OC + 4]; // (w4,w5),(w6,w7)
            ffma2(acc[0][0], vd0, wa.x);
            ffma2(acc[0][1], vd0, wa.y);
            ffma2(acc[0][2], vd0, wb.x);
            ffma2(acc[0][3], vd0, wb.y);
            ffma2(acc[1][0], vd1, wa.x);
            ffma2(acc[1][1], vd1, wa.y);
            ffma2(acc[1][2], vd1, wb.x);
            ffma2(acc[1][3], vd1, wb.y);
            ffma2(acc[2][0], vd2, wa.x);
            ffma2(acc[2][1], vd2, wa.y);
            ffma2(acc[2][2], vd2, wb.x);
            ffma2(acc[2][3], vd2, wb.y);
            ffma2(acc[3][0], vd3, wa.x);
            ffma2(acc[3][1], vd3, wa.y);
            ffma2(acc[3][2], vd3, wb.x);
            ffma2(acc[3][3], vd3, wb.y);
        }
    }

    // epilogue: out is NCHW; lanes write consecutive w -> coalesced
    int ob = warp*8;
#pragma unroll
    for (int jp = 0; jp < 4; jp++) {
        float bias0 = b_dcn[ob + 2*jp];
        float bias1 = b_dcn[ob + 2*jp + 1];
        float* dst0 = &out[(((size_t)(b*OC + ob + 2*jp    ))*HH + h)*WW];
        float* dst1 = &out[(((size_t)(b*OC + ob + 2*jp + 1))*HH + h)*WW];
#pragma unroll
        for (int i = 0; i < 4; i++) {
            float2 r = unpack2(acc[i][jp]);
            dst0[lane + 32*i] = r.x + bias0;
            dst1[lane + 32*i] = r.y + bias1;
        }
    }
}

// ============ launch ============
extern "C" void kernel_launch(void* const* d_in, const int* in_sizes, int n_in,
                              void* d_out, int out_size) {
    const float* x     = (const float*)d_in[0];
    const float* w_off = (const float*)d_in[1];
    const float* b_off = (const float*)d_in[2];
    const float* w_dcn = (const float*)d_in[3];
    const float* b_dcn = (const float*)d_in[4];
    float* out = (float*)d_out;

    const int SMEM_OFF = (4*SXROW + K2*CH*20) * 4;         // 179200 B
    const int SMEM_DEF = (64*VP + 64*OC) * 4;              // 49408 B
    cudaFuncSetAttribute(k_offconv, cudaFuncAttributeMaxDynamicSharedMemorySize, SMEM_OFF);
    cudaFuncSetAttribute(k_deform,  cudaFuncAttributeMaxDynamicSharedMemorySize, SMEM_DEF);

    k_transpose<<<dim3(WW/32, CH/32, BATCH*HH), dim3(32,8)>>>(x);
    k_reorder<<<64, 256>>>(w_off, w_dcn);
    k_offconv<<<BATCH*HH/2, 256, SMEM_OFF>>>(b_off);
    k_deform<<<BATCH*HH, 256, SMEM_DEF>>>(b_dcn, out);
}

// round 6
// speedup vs baseline: 1.5650x; 1.1407x over previous
#include <cuda_runtime.h>
#include <cuda_bf16.h>
#include <math.h>
#include <stdint.h>

#define BATCH 4
#define CH 64
#define OC 64
#define HH 128
#define WW 128
#define HW (HH*WW)
#define PIX (BATCH*HW)
#define K2 9
#define KKD 576            // K2*CH
#define SXROW (WW*65)      // padded row stride in floats (8320)

// -------- device scratch (no allocations allowed) --------
__device__ float g_xn[PIX*CH];            // x in NHWC: [b][h][w][c]
__device__ float g_offs[PIX*18];          // offsets: [pix][18]
__device__ float g_wor[K2*CH*20];         // offset-conv weights: [k][c][p padded to 20]
__device__ unsigned g_wmma_hi[K2*2048];   // deform weights bf16 hi: per-k 64ch x 64oc, ldmatrix-swizzled
__device__ unsigned g_wmma_lo[K2*2048];   // deform weights bf16 lo

// single dynamic-shared symbol shared by all kernels
extern __shared__ char smraw[];

// ---- packed helpers ----
__device__ __forceinline__ void ffma2(unsigned long long &acc, unsigned long long a, unsigned long long b) {
    asm("fma.rn.f32x2 %0, %1, %2, %0;" : "+l"(acc) : "l"(a), "l"(b));
}
__device__ __forceinline__ unsigned long long dup2(float v) {
    unsigned long long r;
    asm("mov.b64 %0, {%1, %1};" : "=l"(r) : "f"(v));
    return r;
}
__device__ __forceinline__ unsigned long long pack2(float a, float b) {
    unsigned long long r;
    asm("mov.b64 %0, {%1, %2};" : "=l"(r) : "f"(a), "f"(b));
    return r;
}
__device__ __forceinline__ float2 unpack2(unsigned long long a) {
    float2 r;
    asm("mov.b64 {%0, %1}, %2;" : "=f"(r.x), "=f"(r.y) : "l"(a));
    return r;
}
// pack two fp32 -> bf16x2 (first arg -> lower 16 bits)
__device__ __forceinline__ unsigned pk_bf16x2(float lo, float hi) {
    unsigned r;
    asm("cvt.rn.bf16x2.f32 %0, %1, %2;" : "=r"(r) : "f"(hi), "f"(lo));
    return r;
}

// ---- mma.sync helpers (HMMA path, supported on plain sm_103 target) ----
__device__ __forceinline__ uint32_t smem_u32(const void* p) {
    uint32_t a;
    asm("{ .reg .u64 t; cvta.to.shared.u64 t, %1; cvt.u32.u64 %0, t; }" : "=r"(a) : "l"(p));
    return a;
}
__device__ __forceinline__ void ldsm4(uint32_t* r, uint32_t addr) {
    asm volatile("ldmatrix.sync.aligned.m8n8.x4.shared.b16 {%0,%1,%2,%3}, [%4];"
        : "=r"(r[0]), "=r"(r[1]), "=r"(r[2]), "=r"(r[3]) : "r"(addr));
}
__device__ __forceinline__ void ldsm4t(uint32_t* r, uint32_t addr) {
    asm volatile("ldmatrix.sync.aligned.m8n8.x4.trans.shared.b16 {%0,%1,%2,%3}, [%4];"
        : "=r"(r[0]), "=r"(r[1]), "=r"(r[2]), "=r"(r[3]) : "r"(addr));
}
__device__ __forceinline__ void mma16816(float* c, const uint32_t* a, uint32_t b0, uint32_t b1) {
    asm volatile("mma.sync.aligned.m16n8k16.row.col.f32.bf16.bf16.f32 "
        "{%0,%1,%2,%3}, {%4,%5,%6,%7}, {%8,%9}, {%0,%1,%2,%3};"
        : "+f"(c[0]), "+f"(c[1]), "+f"(c[2]), "+f"(c[3])
        : "r"(a[0]), "r"(a[1]), "r"(a[2]), "r"(a[3]), "r"(b0), "r"(b1));
}

// ============ kernel 1: NCHW -> NHWC transpose ============
__global__ void k_transpose(const float* __restrict__ x) {
    __shared__ float tile[32][33];
    int bh = blockIdx.z;                 // b*128 + h
    int c0 = blockIdx.y * 32;
    int w0 = blockIdx.x * 32;
    int b = bh >> 7, h = bh & 127;
    int tx = threadIdx.x, ty = threadIdx.y;
#pragma unroll
    for (int i = 0; i < 4; i++) {
        int c = c0 + ty + i*8;
        tile[ty + i*8][tx] = x[((b*CH + c)*HH + h)*WW + w0 + tx];
    }
    __syncthreads();
#pragma unroll
    for (int i = 0; i < 4; i++) {
        int w = w0 + ty + i*8;
        g_xn[(bh*WW + w)*CH + c0 + tx] = tile[tx][ty + i*8];
    }
}

// ============ kernel 2: weight reorder ============
// B plane layout (per kernel position, per hi/lo): row = input channel ch
// (0..63), 64 oc bf16 = 128B per row, 16B chunks xor-swizzled by (ch & 7).
__global__ void k_reorder(const float* __restrict__ w_off, const float* __restrict__ w_dcn) {
    int t = blockIdx.x*blockDim.x + threadIdx.x;
    int stride = gridDim.x*blockDim.x;
    for (int idx = t; idx < K2*CH*20; idx += stride) {
        int row = idx / 20, p = idx - row*20;
        int k = row >> 6, c = row & 63;
        g_wor[idx] = (p < 18) ? w_off[p*KKD + c*K2 + k] : 0.f;
    }
    for (int idx = t; idx < K2*CH*32; idx += stride) {
        int kpos = idx / (CH*32);
        int rem = idx - kpos*(CH*32);
        int ch = rem >> 5;
        int op = rem & 31;        // oc pair index
        int oc = op*2;
        float w0 = w_dcn[oc*KKD + ch*K2 + kpos];
        float w1 = w_dcn[(oc+1)*KKD + ch*K2 + kpos];
        unsigned h2 = pk_bf16x2(w0, w1);
        float h0 = __uint_as_float(h2 << 16);
        float h1 = __uint_as_float(h2 & 0xFFFF0000u);
        unsigned l2 = pk_bf16x2(w0 - h0, w1 - h1);
        int word = ch*32 + (((op >> 2) ^ (ch & 7)) << 2) + (op & 3);
        g_wmma_hi[kpos*2048 + word] = h2;
        g_wmma_lo[kpos*2048 + word] = l2;
    }
}

// ============ kernel 3: offset conv (C=64 -> 18, 3x3, pad1), f32x2 ============
__global__ void k_offconv(const float* __restrict__ b_off) {
    float* smf = (float*)smraw;
    float* sx = smf;                    // 4 * SXROW floats
    float* sw = smf + 4*SXROW;          // 11520 floats
    int blk = blockIdx.x;               // b*64 + h2
    int b = blk >> 6, h2 = blk & 63;
    int t = threadIdx.x;                // 256

    for (int i = t; i < K2*CH*20; i += 256) sw[i] = g_wor[i];

    int ybase = 2*h2 - 1;               // rows ybase .. ybase+3 staged
#pragma unroll
    for (int r = 0; r < 4; r++) {
        int y = ybase + r;
        bool vy = (y >= 0) && (y < HH);
        const float* src = &g_xn[((size_t)(b*HH + y))*WW*CH];
        for (int i = t; i < WW*CH; i += 256) {
            int w = i >> 6, c = i & 63;
            sx[r*SXROW + w*65 + c] = vy ? src[i] : 0.f;
        }
    }
    __syncthreads();

    int rsel = t >> 7;                  // 0 or 1: which output row
    int w = t & 127;
    unsigned long long acc[9];
#pragma unroll
    for (int p = 0; p < 9; p++) acc[p] = pack2(b_off[2*p], b_off[2*p+1]);

#pragma unroll
    for (int ky = 0; ky < 3; ky++) {
#pragma unroll
        for (int kx = 0; kx < 3; kx++) {
            int xx = w + kx - 1;
            if (xx < 0 || xx >= WW) continue;
            const float* xr = &sx[(rsel + ky)*SXROW + xx*65];
            const float* wb = &sw[(ky*3 + kx)*CH*20];
            for (int c = 0; c < CH; c++) {
                unsigned long long xv = dup2(xr[c]);
                const float* wp = wb + c*20;
                ulonglong2 p01 = *(const ulonglong2*)(wp + 0);
                ulonglong2 p23 = *(const ulonglong2*)(wp + 4);
                ulonglong2 p45 = *(const ulonglong2*)(wp + 8);
                ulonglong2 p67 = *(const ulonglong2*)(wp + 12);
                unsigned long long p8 = *(const unsigned long long*)(wp + 16);
                ffma2(acc[0], xv, p01.x);
                ffma2(acc[1], xv, p01.y);
                ffma2(acc[2], xv, p23.x);
                ffma2(acc[3], xv, p23.y);
                ffma2(acc[4], xv, p45.x);
                ffma2(acc[5], xv, p45.y);
                ffma2(acc[6], xv, p67.x);
                ffma2(acc[7], xv, p67.y);
                ffma2(acc[8], xv, p8);
            }
        }
    }
    int h = 2*h2 + rsel;
    float* dst = &g_offs[((size_t)((b*HH + h)*WW + w))*18];
#pragma unroll
    for (int p = 0; p < 9; p++) {
        float2 r = unpack2(acc[p]);
        dst[2*p]   = r.x;
        dst[2*p+1] = r.y;
    }
}

// ============ kernel 4: deformable conv v5 (mma.sync bf16 split GEMM) ============
// Block: 256 threads = 8 warps, 128 pixels (one image row), 64 oc.
// Per kernel position: gather bilinear vals -> bf16 hi/lo A planes (warp-local
// 16-px tiles), copy pre-swizzled B hi/lo (64x64), then each warp does
// m16 x n64 x k64 with 3-term split via mma.sync (96 HMMA per position).
#define SMA_HI 0
#define SMA_LO 16384
#define SMB_HI 32768
#define SMB_LO 40960
#define SMEM_DEF 49152

__global__ void __launch_bounds__(256)
k_deform(const float* __restrict__ b_dcn, float* __restrict__ out) {
    char* sm = smraw;
    uint32_t sb = smem_u32(sm);
    int t = threadIdx.x;
    int lane = t & 31, warp = t >> 5;   // warp in [0,8)
    int blk = blockIdx.x;               // b*128 + h
    int b = blk >> 7, h = blk & 127;
    int pix0 = blk * WW;
    const float* xb = &g_xn[(size_t)b * (HW*CH)];

    float acc[8][4];
#pragma unroll
    for (int i = 0; i < 8; i++)
#pragma unroll
        for (int j = 0; j < 4; j++) acc[i][j] = 0.f;

    // per-lane ldmatrix address components (shared across iterations)
    int ltile = lane >> 3, lrow = lane & 7;
    // A: row within warp tile, chunk parity
    int a_r = (ltile & 1)*8 + lrow;            // 0..15
    int a_gr = warp*16 + a_r;                  // global A row
    int a_cpar = ltile >> 1;                   // 0/1: k-chunk within k16
    uint32_t a_base = sb + a_gr*128;
    // B: k row, n-chunk parity
    int b_koff = (ltile & 1)*8 + lrow;         // k row offset within k16
    int b_npar = ltile >> 1;

    for (int k = 0; k < K2; k++) {
        __syncthreads();                // all warps done reading previous B

        // stage B hi/lo (pre-swizzled): 2048 words each
        {
            const uint4* shi = (const uint4*)&g_wmma_hi[k*2048];
            const uint4* slo = (const uint4*)&g_wmma_lo[k*2048];
            uint4* dhi = (uint4*)(sm + SMB_HI);
            uint4* dlo = (uint4*)(sm + SMB_LO);
            dhi[t]       = shi[t];
            dhi[t + 256] = shi[t + 256];
            dlo[t]       = slo[t];
            dlo[t + 256] = slo[t + 256];
        }

        // gather: warp handles its own 16 pixels (rows it will consume)
        int ky = k / 3, kx = k - ky*3;
        int c2 = lane*2;
        unsigned swz = (((lane >> 2) ^ 0) << 4) + ((lane & 3) << 2); // chunk part filled per-p below
#pragma unroll 2
        for (int j = 0; j < 16; j++) {
            int p = warp*16 + j;
            int pix = pix0 + p;
            float dy = g_offs[pix*18 + 2*k];
            float dx = g_offs[pix*18 + 2*k + 1];
            float py = (float)(h + ky - 1) + dy;
            float px = (float)(p + kx - 1) + dx;
            float y0f = floorf(py), x0f = floorf(px);
            float wy = py - y0f, wx = px - x0f;
            int y0 = (int)y0f, x0 = (int)x0f;
            bool vy0 = (y0 >= 0) && (y0 < HH);
            bool vy1 = (y0 >= -1) && (y0 < HH-1);
            bool vx0 = (x0 >= 0) && (x0 < WW);
            bool vx1 = (x0 >= -1) && (x0 < WW-1);
            int a00 = ((y0  )*WW + x0    )*CH + c2;
            int a01 = ((y0  )*WW + x0 + 1)*CH + c2;
            int a10 = ((y0+1)*WW + x0    )*CH + c2;
            int a11 = ((y0+1)*WW + x0 + 1)*CH + c2;
            float2 v00 = make_float2(0.f,0.f), v01 = v00, v10 = v00, v11 = v00;
            if (vy0 && vx0) v00 = *(const float2*)&xb[a00];
            if (vy0 && vx1) v01 = *(const float2*)&xb[a01];
            if (vy1 && vx0) v10 = *(const float2*)&xb[a10];
            if (vy1 && vx1) v11 = *(const float2*)&xb[a11];
            float w00 = (1.f-wy)*(1.f-wx), w01 = (1.f-wy)*wx;
            float w10 = wy*(1.f-wx),       w11 = wy*wx;
            float r0 = w00*v00.x + w01*v01.x + w10*v10.x + w11*v11.x;
            float r1 = w00*v00.y + w01*v01.y + w10*v10.y + w11*v11.y;
            unsigned h2 = pk_bf16x2(r0, r1);
            float h0 = __uint_as_float(h2 << 16);
            float h1 = __uint_as_float(h2 & 0xFFFF0000u);
            unsigned l2 = pk_bf16x2(r0 - h0, r1 - h1);
            unsigned off = p*128 + ((((lane >> 2) ^ (p & 7)) << 4) | ((lane & 3) << 2));
            *(unsigned*)(sm + SMA_HI + off) = h2;
            *(unsigned*)(sm + SMA_LO + off) = l2;
        }
        __syncthreads();

        // GEMM: m16 x n64 x k64, 3-term bf16 split
#pragma unroll
        for (int kt = 0; kt < 4; kt++) {
            uint32_t aH[4], aL[4];
            {
                int chunkk = 2*kt + a_cpar;
                uint32_t addr = a_base + ((chunkk ^ (a_gr & 7)) << 4);
                ldsm4(aH, addr + SMA_HI);
                ldsm4(aL, addr + SMA_LO);
            }
#pragma unroll
            for (int ng = 0; ng < 4; ng++) {      // n16 groups
                uint32_t bH[4], bL[4];
                {
                    int kk = kt*16 + b_koff;
                    int chunkn = 2*ng + b_npar;
                    uint32_t addr = sb + kk*128 + ((chunkn ^ (kk & 7)) << 4);
                    ldsm4t(bH, addr + SMB_HI);
                    ldsm4t(bL, addr + SMB_LO);
                }
                mma16816(acc[2*ng],   aH, bH[0], bH[1]);
                mma16816(acc[2*ng],   aL, bH[0], bH[1]);
                mma16816(acc[2*ng],   aH, bL[0], bL[1]);
                mma16816(acc[2*ng+1], aH, bH[2], bH[3]);
                mma16816(acc[2*ng+1], aL, bH[2], bH[3]);
                mma16816(acc[2*ng+1], aH, bL[2], bL[3]);
            }
        }
    }

    // epilogue: write fragments to NCHW out
    int r0 = lane >> 2;                 // 0..7
    int cq = (lane & 3)*2;
    int w0 = warp*16 + r0;
    size_t obase = (size_t)b*OC*HW + (size_t)h*WW;
#pragma unroll
    for (int nt = 0; nt < 8; nt++) {
        int oc = nt*8 + cq;
        float bias0 = b_dcn[oc];
        float bias1 = b_dcn[oc+1];
        float* o0 = &out[obase + (size_t)oc*HW];
        float* o1 = &out[obase + (size_t)(oc+1)*HW];
        o0[w0]     = acc[nt][0] + bias0;
        o1[w0]     = acc[nt][1] + bias1;
        o0[w0 + 8] = acc[nt][2] + bias0;
        o1[w0 + 8] = acc[nt][3] + bias1;
    }
}

// ============ launch ============
extern "C" void kernel_launch(void* const* d_in, const int* in_sizes, int n_in,
                              void* d_out, int out_size) {
    const float* x     = (const float*)d_in[0];
    const float* w_off = (const float*)d_in[1];
    const float* b_off = (const float*)d_in[2];
    const float* w_dcn = (const float*)d_in[3];
    const float* b_dcn = (const float*)d_in[4];
    float* out = (float*)d_out;

    const int SMEM_OFF = (4*SXROW + K2*CH*20) * 4;         // 179200 B
    cudaFuncSetAttribute(k_offconv, cudaFuncAttributeMaxDynamicSharedMemorySize, SMEM_OFF);
    cudaFuncSetAttribute(k_deform,  cudaFuncAttributeMaxDynamicSharedMemorySize, SMEM_DEF);

    k_transpose<<<dim3(WW/32, CH/32, BATCH*HH), dim3(32,8)>>>(x);
    k_reorder<<<64, 256>>>(w_off, w_dcn);
    k_offconv<<<BATCH*HH/2, 256, SMEM_OFF>>>(b_off);
    k_deform<<<BATCH*HH, 256, SMEM_DEF>>>(b_dcn, out);
}

// round 7
// speedup vs baseline: 1.8311x; 1.1701x over previous
#include <cuda_runtime.h>
#include <cuda_bf16.h>
#include <math.h>
#include <stdint.h>

#define BATCH 4
#define CH 64
#define OC 64
#define HH 128
#define WW 128
#define HW (HH*WW)
#define PIX (BATCH*HW)
#define K2 9
#define KKD 576            // K2*CH
#define SXROW (WW*65)      // padded row stride in floats (8320)

// -------- device scratch (no allocations allowed) --------
__device__ float g_xn[PIX*CH];            // x in NHWC: [b][h][w][c]
__device__ float g_offs[PIX*18];          // offsets: [pix][18]
__device__ float g_wor[K2*CH*20];         // offset-conv weights: [k][c][p padded to 20]
__device__ uint4 g_wfragH[K2*512];        // B hi fragments: [k][kt*4+ng][lane]
__device__ uint4 g_wfragL[K2*512];        // B lo fragments
__device__ float4 g_pw[PIX*K2];           // bilinear weights (validity folded)
__device__ int4  g_po[PIX*K2];            // per-corner clamped byte offsets

// single dynamic-shared symbol shared by all kernels
extern __shared__ char smraw[];

// ---- packed helpers ----
__device__ __forceinline__ void ffma2(unsigned long long &acc, unsigned long long a, unsigned long long b) {
    asm("fma.rn.f32x2 %0, %1, %2, %0;" : "+l"(acc) : "l"(a), "l"(b));
}
__device__ __forceinline__ unsigned long long dup2(float v) {
    unsigned long long r;
    asm("mov.b64 %0, {%1, %1};" : "=l"(r) : "f"(v));
    return r;
}
__device__ __forceinline__ unsigned long long pack2(float a, float b) {
    unsigned long long r;
    asm("mov.b64 %0, {%1, %2};" : "=l"(r) : "f"(a), "f"(b));
    return r;
}
__device__ __forceinline__ float2 unpack2(unsigned long long a) {
    float2 r;
    asm("mov.b64 {%0, %1}, %2;" : "=f"(r.x), "=f"(r.y) : "l"(a));
    return r;
}
// pack two fp32 -> bf16x2 (first arg -> lower 16 bits)
__device__ __forceinline__ unsigned pk_bf16x2(float lo, float hi) {
    unsigned r;
    asm("cvt.rn.bf16x2.f32 %0, %1, %2;" : "=r"(r) : "f"(hi), "f"(lo));
    return r;
}

// ---- mma.sync helpers ----
__device__ __forceinline__ uint32_t smem_u32(const void* p) {
    uint32_t a;
    asm("{ .reg .u64 t; cvta.to.shared.u64 t, %1; cvt.u32.u64 %0, t; }" : "=r"(a) : "l"(p));
    return a;
}
__device__ __forceinline__ void ldsm4(uint32_t* r, uint32_t addr) {
    asm volatile("ldmatrix.sync.aligned.m8n8.x4.shared.b16 {%0,%1,%2,%3}, [%4];"
        : "=r"(r[0]), "=r"(r[1]), "=r"(r[2]), "=r"(r[3]) : "r"(addr));
}
__device__ __forceinline__ void mma16816(float* c, const uint32_t* a, uint32_t b0, uint32_t b1) {
    asm volatile("mma.sync.aligned.m16n8k16.row.col.f32.bf16.bf16.f32 "
        "{%0,%1,%2,%3}, {%4,%5,%6,%7}, {%8,%9}, {%0,%1,%2,%3};"
        : "+f"(c[0]), "+f"(c[1]), "+f"(c[2]), "+f"(c[3])
        : "r"(a[0]), "r"(a[1]), "r"(a[2]), "r"(a[3]), "r"(b0), "r"(b1));
}

// ============ kernel 1: NCHW -> NHWC transpose ============
__global__ void k_transpose(const float* __restrict__ x) {
    __shared__ float tile[32][33];
    int bh = blockIdx.z;                 // b*128 + h
    int c0 = blockIdx.y * 32;
    int w0 = blockIdx.x * 32;
    int b = bh >> 7, h = bh & 127;
    int tx = threadIdx.x, ty = threadIdx.y;
#pragma unroll
    for (int i = 0; i < 4; i++) {
        int c = c0 + ty + i*8;
        tile[ty + i*8][tx] = x[((b*CH + c)*HH + h)*WW + w0 + tx];
    }
    __syncthreads();
#pragma unroll
    for (int i = 0; i < 4; i++) {
        int w = w0 + ty + i*8;
        g_xn[(bh*WW + w)*CH + c0 + tx] = tile[tx][ty + i*8];
    }
}

// ============ kernel 2: weight reorder ============
// Build B fragments directly in the mma.sync m16n8k16 register layout:
// lane l, reg0: b[k0..k0+1][n], k0=(l&3)*2, n=(l>>2); reg1: k0+8; reg2/3: n+8.
__global__ void k_reorder(const float* __restrict__ w_off, const float* __restrict__ w_dcn) {
    int t = blockIdx.x*blockDim.x + threadIdx.x;
    int stride = gridDim.x*blockDim.x;
    for (int idx = t; idx < K2*CH*20; idx += stride) {
        int row = idx / 20, p = idx - row*20;
        int k = row >> 6, c = row & 63;
        g_wor[idx] = (p < 18) ? w_off[p*KKD + c*K2 + k] : 0.f;
    }
    for (int idx = t; idx < K2*512; idx += stride) {
        int kpos = idx / 512;
        int rem = idx & 511;
        int tile = rem >> 5;        // kt*4 + ng
        int lane = rem & 31;
        int kt = tile >> 2, ng = tile & 3;
        int n0 = ng*16 + (lane >> 2);
        int k0 = kt*16 + (lane & 3)*2;
        uint4 hi, lo;
        unsigned hw_, lw_;
        float a0, a1, h0, h1;
#define MKFRAG(KK, NN, HRES, LRES) \
        a0 = w_dcn[(NN)*KKD + (KK)*K2 + kpos]; \
        a1 = w_dcn[(NN)*KKD + (KK+1)*K2 + kpos]; \
        hw_ = pk_bf16x2(a0, a1); \
        h0 = __uint_as_float(hw_ << 16); \
        h1 = __uint_as_float(hw_ & 0xFFFF0000u); \
        lw_ = pk_bf16x2(a0 - h0, a1 - h1); \
        HRES = hw_; LRES = lw_;
        MKFRAG(k0,     n0,     hi.x, lo.x)
        MKFRAG(k0 + 8, n0,     hi.y, lo.y)
        MKFRAG(k0,     n0 + 8, hi.z, lo.z)
        MKFRAG(k0 + 8, n0 + 8, hi.w, lo.w)
#undef MKFRAG
        g_wfragH[idx] = hi;
        g_wfragL[idx] = lo;
    }
}

// ============ kernel 3: offset conv (C=64 -> 18, 3x3, pad1), f32x2 ============
__global__ void k_offconv(const float* __restrict__ b_off) {
    float* smf = (float*)smraw;
    float* sx = smf;                    // 4 * SXROW floats
    float* sw = smf + 4*SXROW;          // 11520 floats
    int blk = blockIdx.x;               // b*64 + h2
    int b = blk >> 6, h2 = blk & 63;
    int t = threadIdx.x;                // 256

    for (int i = t; i < K2*CH*20; i += 256) sw[i] = g_wor[i];

    int ybase = 2*h2 - 1;               // rows ybase .. ybase+3 staged
#pragma unroll
    for (int r = 0; r < 4; r++) {
        int y = ybase + r;
        bool vy = (y >= 0) && (y < HH);
        const float* src = &g_xn[((size_t)(b*HH + y))*WW*CH];
        for (int i = t; i < WW*CH; i += 256) {
            int w = i >> 6, c = i & 63;
            sx[r*SXROW + w*65 + c] = vy ? src[i] : 0.f;
        }
    }
    __syncthreads();

    int rsel = t >> 7;                  // 0 or 1: which output row
    int w = t & 127;
    unsigned long long acc[9];
#pragma unroll
    for (int p = 0; p < 9; p++) acc[p] = pack2(b_off[2*p], b_off[2*p+1]);

#pragma unroll
    for (int ky = 0; ky < 3; ky++) {
#pragma unroll
        for (int kx = 0; kx < 3; kx++) {
            int xx = w + kx - 1;
            if (xx < 0 || xx >= WW) continue;
            const float* xr = &sx[(rsel + ky)*SXROW + xx*65];
            const float* wb = &sw[(ky*3 + kx)*CH*20];
            for (int c = 0; c < CH; c++) {
                unsigned long long xv = dup2(xr[c]);
                const float* wp = wb + c*20;
                ulonglong2 p01 = *(const ulonglong2*)(wp + 0);
                ulonglong2 p23 = *(const ulonglong2*)(wp + 4);
                ulonglong2 p45 = *(const ulonglong2*)(wp + 8);
                ulonglong2 p67 = *(const ulonglong2*)(wp + 12);
                unsigned long long p8 = *(const unsigned long long*)(wp + 16);
                ffma2(acc[0], xv, p01.x);
                ffma2(acc[1], xv, p01.y);
                ffma2(acc[2], xv, p23.x);
                ffma2(acc[3], xv, p23.y);
                ffma2(acc[4], xv, p45.x);
                ffma2(acc[5], xv, p45.y);
                ffma2(acc[6], xv, p67.x);
                ffma2(acc[7], xv, p67.y);
                ffma2(acc[8], xv, p8);
            }
        }
    }
    int h = 2*h2 + rsel;
    float* dst = &g_offs[((size_t)((b*HH + h)*WW + w))*18];
#pragma unroll
    for (int p = 0; p < 9; p++) {
        float2 r = unpack2(acc[p]);
        dst[2*p]   = r.x;
        dst[2*p+1] = r.y;
    }
}

// ============ kernel 3.5: bilinear precompute ============
// For every (pix, k): weights with validity folded in, 4 clamped corner
// byte-offsets. Hot kernel then does 4 unconditional loads + 8 FFMA.
__global__ void k_precomp() {
    int idx = blockIdx.x*blockDim.x + threadIdx.x;
    if (idx >= PIX*K2) return;
    int pix = idx / K2, k = idx - pix*K2;
    int hw = pix & (HW-1);
    int h = hw >> 7, w = hw & 127;
    float dy = g_offs[pix*18 + 2*k];
    float dx = g_offs[pix*18 + 2*k + 1];
    int ky = k / 3, kx = k - ky*3;
    float py = (float)(h + ky - 1) + dy;
    float px = (float)(w + kx - 1) + dx;
    float y0f = floorf(py), x0f = floorf(px);
    float wy = py - y0f, wx = px - x0f;
    int y0 = (int)y0f, x0 = (int)x0f;
    bool vy0 = (y0 >= 0) && (y0 < HH);
    bool vy1 = (y0 >= -1) && (y0 < HH-1);
    bool vx0 = (x0 >= 0) && (x0 < WW);
    bool vx1 = (x0 >= -1) && (x0 < WW-1);
    int iy0 = min(max(y0, 0), HH-1), iy1 = min(max(y0+1, 0), HH-1);
    int ix0 = min(max(x0, 0), WW-1), ix1 = min(max(x0+1, 0), WW-1);
    float4 wv;
    wv.x = (vy0 && vx0) ? (1.f-wy)*(1.f-wx) : 0.f;
    wv.y = (vy0 && vx1) ? (1.f-wy)*wx       : 0.f;
    wv.z = (vy1 && vx0) ? wy*(1.f-wx)       : 0.f;
    wv.w = (vy1 && vx1) ? wy*wx             : 0.f;
    int4 ov;
    ov.x = (iy0*WW + ix0)*CH*4;
    ov.y = (iy0*WW + ix1)*CH*4;
    ov.z = (iy1*WW + ix0)*CH*4;
    ov.w = (iy1*WW + ix1)*CH*4;
    g_pw[idx] = wv;
    g_po[idx] = ov;
}

// ============ kernel 4: deformable conv v6 (mma.sync, no block syncs) ============
// Block: 256 threads = 8 warps, 128 pixels (one image row), 64 oc.
// A tiles are warp-private smem rows; B fragments stream from gmem (L1-hot).
// Loop per position: gather (precomputed weights/addrs) -> syncwarp ->
// ldsm A + LDG B frags + 96 HMMA -> syncwarp. No __syncthreads anywhere.
#define SMA_HI 0
#define SMA_LO 16384
#define SMEM_DEF 32768

__global__ void __launch_bounds__(256)
k_deform(const float* __restrict__ b_dcn, float* __restrict__ out) {
    char* sm = smraw;
    uint32_t sb = smem_u32(sm);
    int t = threadIdx.x;
    int lane = t & 31, warp = t >> 5;   // warp in [0,8)
    int blk = blockIdx.x;               // b*128 + h
    int b = blk >> 7, h = blk & 127;
    int pix0 = blk * WW;
    const char* xc = (const char*)&g_xn[(size_t)b * (HW*CH)];
    int lb = lane*8;                    // channel byte offset (2 floats per lane)

    float acc[8][4];
#pragma unroll
    for (int i = 0; i < 8; i++)
#pragma unroll
        for (int j = 0; j < 4; j++) acc[i][j] = 0.f;

    // ldmatrix A address components
    int ltile = lane >> 3, lrow = lane & 7;
    int a_r = (ltile & 1)*8 + lrow;            // 0..15
    int a_gr = warp*16 + a_r;                  // global A row
    int a_cpar = ltile >> 1;                   // 0/1: chunk parity in k16
    uint32_t a_base = sb + a_gr*128;

    for (int k = 0; k < K2; k++) {
        // ---- gather 16 warp-local pixels ----
        const float4* pwb = &g_pw[(size_t)(pix0 + warp*16)*K2 + k];
        const int4*   pob = &g_po[(size_t)(pix0 + warp*16)*K2 + k];
#pragma unroll 4
        for (int j = 0; j < 16; j++) {
            int p = warp*16 + j;
            float4 wv = pwb[j*K2];
            int4   ov = pob[j*K2];
            float2 v00 = *(const float2*)(xc + ov.x + lb);
            float2 v01 = *(const float2*)(xc + ov.y + lb);
            float2 v10 = *(const float2*)(xc + ov.z + lb);
            float2 v11 = *(const float2*)(xc + ov.w + lb);
            float r0 = wv.x*v00.x + wv.y*v01.x + wv.z*v10.x + wv.w*v11.x;
            float r1 = wv.x*v00.y + wv.y*v01.y + wv.z*v10.y + wv.w*v11.y;
            unsigned h2 = pk_bf16x2(r0, r1);
            float h0 = __uint_as_float(h2 << 16);
            float h1 = __uint_as_float(h2 & 0xFFFF0000u);
            unsigned l2 = pk_bf16x2(r0 - h0, r1 - h1);
            unsigned off = p*128 + ((((lane >> 2) ^ (p & 7)) << 4) | ((lane & 3) << 2));
            *(unsigned*)(sm + SMA_HI + off) = h2;
            *(unsigned*)(sm + SMA_LO + off) = l2;
        }
        __syncwarp();

        // ---- GEMM: m16 x n64 x k64, 3-term bf16 split ----
        const uint4* bfH = &g_wfragH[k*512 + lane];
        const uint4* bfL = &g_wfragL[k*512 + lane];
#pragma unroll
        for (int kt = 0; kt < 4; kt++) {
            uint32_t aH[4], aL[4];
            int chunkk = 2*kt + a_cpar;
            uint32_t addr = a_base + ((chunkk ^ (a_gr & 7)) << 4);
            ldsm4(aH, addr + SMA_HI);
            ldsm4(aL, addr + SMA_LO);
#pragma unroll
            for (int ng = 0; ng < 4; ng++) {
                uint4 BH = bfH[(kt*4 + ng)*32];
                uint4 BL = bfL[(kt*4 + ng)*32];
                mma16816(acc[2*ng],   aH, BH.x, BH.y);
                mma16816(acc[2*ng],   aL, BH.x, BH.y);
                mma16816(acc[2*ng],   aH, BL.x, BL.y);
                mma16816(acc[2*ng+1], aH, BH.z, BH.w);
                mma16816(acc[2*ng+1], aL, BH.z, BH.w);
                mma16816(acc[2*ng+1], aH, BL.z, BL.w);
            }
        }
        __syncwarp();                   // all lanes done with A before overwrite
    }

    // epilogue: write fragments to NCHW out
    int r0 = lane >> 2;                 // 0..7
    int cq = (lane & 3)*2;
    int w0 = warp*16 + r0;
    size_t obase = (size_t)b*OC*HW + (size_t)h*WW;
#pragma unroll
    for (int nt = 0; nt < 8; nt++) {
        int oc = nt*8 + cq;
        float bias0 = b_dcn[oc];
        float bias1 = b_dcn[oc+1];
        float* o0 = &out[obase + (size_t)oc*HW];
        float* o1 = &out[obase + (size_t)(oc+1)*HW];
        o0[w0]     = acc[nt][0] + bias0;
        o1[w0]     = acc[nt][1] + bias1;
        o0[w0 + 8] = acc[nt][2] + bias0;
        o1[w0 + 8] = acc[nt][3] + bias1;
    }
}

// ============ launch ============
extern "C" void kernel_launch(void* const* d_in, const int* in_sizes, int n_in,
                              void* d_out, int out_size) {
    const float* x     = (const float*)d_in[0];
    const float* w_off = (const float*)d_in[1];
    const float* b_off = (const float*)d_in[2];
    const float* w_dcn = (const float*)d_in[3];
    const float* b_dcn = (const float*)d_in[4];
    float* out = (float*)d_out;

    const int SMEM_OFF = (4*SXROW + K2*CH*20) * 4;         // 179200 B
    cudaFuncSetAttribute(k_offconv, cudaFuncAttributeMaxDynamicSharedMemorySize, SMEM_OFF);
    cudaFuncSetAttribute(k_deform,  cudaFuncAttributeMaxDynamicSharedMemorySize, SMEM_DEF);

    k_transpose<<<dim3(WW/32, CH/32, BATCH*HH), dim3(32,8)>>>(x);
    k_reorder<<<64, 256>>>(w_off, w_dcn);
    k_offconv<<<BATCH*HH/2, 256, SMEM_OFF>>>(b_off);
    k_precomp<<<(PIX*K2 + 255)/256, 256>>>();
    k_deform<<<BATCH*HH, 256, SMEM_DEF>>>(b_dcn, out);
}

// round 8
// speedup vs baseline: 1.9762x; 1.0792x over previous
#include <cuda_runtime.h>
#include <cuda_bf16.h>
#include <math.h>
#include <stdint.h>

#define BATCH 4
#define CH 64
#define OC 64
#define HH 128
#define WW 128
#define HW (HH*WW)
#define PIX (BATCH*HW)
#define K2 9
#define KKD 576            // K2*CH
#define SXROW (WW*65)      // padded row stride in floats (8320)

// -------- device scratch (no allocations allowed) --------
__device__ float g_xn[PIX*CH];            // x in NHWC: [b][h][w][c]
__device__ float g_offs[PIX*18];          // offsets: [pix][18]
__device__ float g_wor[K2*CH*20];         // offset-conv weights: [k][c][p padded to 20]
__device__ uint4 g_wfragH[K2*512];        // B hi fragments: [k][kt*4+ng][lane]
__device__ uint4 g_wfragL[K2*512];        // B lo fragments
__device__ float4 g_pw[PIX*K2];           // bilinear weights (validity folded)
__device__ int4  g_po[PIX*K2];            // per-corner clamped byte offsets

// single dynamic-shared symbol shared by all kernels
extern __shared__ char smraw[];

// ---- packed helpers ----
__device__ __forceinline__ void ffma2(unsigned long long &acc, unsigned long long a, unsigned long long b) {
    asm("fma.rn.f32x2 %0, %1, %2, %0;" : "+l"(acc) : "l"(a), "l"(b));
}
__device__ __forceinline__ unsigned long long dup2(float v) {
    unsigned long long r;
    asm("mov.b64 %0, {%1, %1};" : "=l"(r) : "f"(v));
    return r;
}
__device__ __forceinline__ unsigned long long pack2(float a, float b) {
    unsigned long long r;
    asm("mov.b64 %0, {%1, %2};" : "=l"(r) : "f"(a), "f"(b));
    return r;
}
__device__ __forceinline__ float2 unpack2(unsigned long long a) {
    float2 r;
    asm("mov.b64 {%0, %1}, %2;" : "=f"(r.x), "=f"(r.y) : "l"(a));
    return r;
}
// pack two fp32 -> bf16x2 (first arg -> lower 16 bits)
__device__ __forceinline__ unsigned pk_bf16x2(float lo, float hi) {
    unsigned r;
    asm("cvt.rn.bf16x2.f32 %0, %1, %2;" : "=r"(r) : "f"(hi), "f"(lo));
    return r;
}

// ---- mma.sync helpers ----
__device__ __forceinline__ uint32_t smem_u32(const void* p) {
    uint32_t a;
    asm("{ .reg .u64 t; cvta.to.shared.u64 t, %1; cvt.u32.u64 %0, t; }" : "=r"(a) : "l"(p));
    return a;
}
__device__ __forceinline__ void ldsm4(uint32_t* r, uint32_t addr) {
    asm volatile("ldmatrix.sync.aligned.m8n8.x4.shared.b16 {%0,%1,%2,%3}, [%4];"
        : "=r"(r[0]), "=r"(r[1]), "=r"(r[2]), "=r"(r[3]) : "r"(addr));
}
__device__ __forceinline__ void mma16816(float* c, const uint32_t* a, uint32_t b0, uint32_t b1) {
    asm volatile("mma.sync.aligned.m16n8k16.row.col.f32.bf16.bf16.f32 "
        "{%0,%1,%2,%3}, {%4,%5,%6,%7}, {%8,%9}, {%0,%1,%2,%3};"
        : "+f"(c[0]), "+f"(c[1]), "+f"(c[2]), "+f"(c[3])
        : "r"(a[0]), "r"(a[1]), "r"(a[2]), "r"(a[3]), "r"(b0), "r"(b1));
}

// ============ kernel 1: NCHW -> NHWC transpose ============
__global__ void k_transpose(const float* __restrict__ x) {
    __shared__ float tile[32][33];
    int bh = blockIdx.z;                 // b*128 + h
    int c0 = blockIdx.y * 32;
    int w0 = blockIdx.x * 32;
    int b = bh >> 7, h = bh & 127;
    int tx = threadIdx.x, ty = threadIdx.y;
#pragma unroll
    for (int i = 0; i < 4; i++) {
        int c = c0 + ty + i*8;
        tile[ty + i*8][tx] = x[((b*CH + c)*HH + h)*WW + w0 + tx];
    }
    __syncthreads();
#pragma unroll
    for (int i = 0; i < 4; i++) {
        int w = w0 + ty + i*8;
        g_xn[(bh*WW + w)*CH + c0 + tx] = tile[tx][ty + i*8];
    }
}

// ============ kernel 2: weight reorder ============
__global__ void k_reorder(const float* __restrict__ w_off, const float* __restrict__ w_dcn) {
    int t = blockIdx.x*blockDim.x + threadIdx.x;
    int stride = gridDim.x*blockDim.x;
    for (int idx = t; idx < K2*CH*20; idx += stride) {
        int row = idx / 20, p = idx - row*20;
        int k = row >> 6, c = row & 63;
        g_wor[idx] = (p < 18) ? w_off[p*KKD + c*K2 + k] : 0.f;
    }
    for (int idx = t; idx < K2*512; idx += stride) {
        int kpos = idx / 512;
        int rem = idx & 511;
        int tile = rem >> 5;        // kt*4 + ng
        int lane = rem & 31;
        int kt = tile >> 2, ng = tile & 3;
        int n0 = ng*16 + (lane >> 2);
        int k0 = kt*16 + (lane & 3)*2;
        uint4 hi, lo;
        unsigned hw_, lw_;
        float a0, a1, h0, h1;
#define MKFRAG(KK, NN, HRES, LRES) \
        a0 = w_dcn[(NN)*KKD + (KK)*K2 + kpos]; \
        a1 = w_dcn[(NN)*KKD + (KK+1)*K2 + kpos]; \
        hw_ = pk_bf16x2(a0, a1); \
        h0 = __uint_as_float(hw_ << 16); \
        h1 = __uint_as_float(hw_ & 0xFFFF0000u); \
        lw_ = pk_bf16x2(a0 - h0, a1 - h1); \
        HRES = hw_; LRES = lw_;
        MKFRAG(k0,     n0,     hi.x, lo.x)
        MKFRAG(k0 + 8, n0,     hi.y, lo.y)
        MKFRAG(k0,     n0 + 8, hi.z, lo.z)
        MKFRAG(k0 + 8, n0 + 8, hi.w, lo.w)
#undef MKFRAG
        g_wfragH[idx] = hi;
        g_wfragL[idx] = lo;
    }
}

// ============ kernel 3: offset conv (C=64 -> 18, 3x3, pad1), f32x2 ============
__global__ void k_offconv(const float* __restrict__ b_off) {
    float* smf = (float*)smraw;
    float* sx = smf;                    // 4 * SXROW floats
    float* sw = smf + 4*SXROW;          // 11520 floats
    int blk = blockIdx.x;               // b*64 + h2
    int b = blk >> 6, h2 = blk & 63;
    int t = threadIdx.x;                // 256

    for (int i = t; i < K2*CH*20; i += 256) sw[i] = g_wor[i];

    int ybase = 2*h2 - 1;               // rows ybase .. ybase+3 staged
#pragma unroll
    for (int r = 0; r < 4; r++) {
        int y = ybase + r;
        bool vy = (y >= 0) && (y < HH);
        const float* src = &g_xn[((size_t)(b*HH + y))*WW*CH];
        for (int i = t; i < WW*CH; i += 256) {
            int w = i >> 6, c = i & 63;
            sx[r*SXROW + w*65 + c] = vy ? src[i] : 0.f;
        }
    }
    __syncthreads();

    int rsel = t >> 7;                  // 0 or 1: which output row
    int w = t & 127;
    unsigned long long acc[9];
#pragma unroll
    for (int p = 0; p < 9; p++) acc[p] = pack2(b_off[2*p], b_off[2*p+1]);

#pragma unroll
    for (int ky = 0; ky < 3; ky++) {
#pragma unroll
        for (int kx = 0; kx < 3; kx++) {
            int xx = w + kx - 1;
            if (xx < 0 || xx >= WW) continue;
            const float* xr = &sx[(rsel + ky)*SXROW + xx*65];
            const float* wb = &sw[(ky*3 + kx)*CH*20];
            for (int c = 0; c < CH; c++) {
                unsigned long long xv = dup2(xr[c]);
                const float* wp = wb + c*20;
                ulonglong2 p01 = *(const ulonglong2*)(wp + 0);
                ulonglong2 p23 = *(const ulonglong2*)(wp + 4);
                ulonglong2 p45 = *(const ulonglong2*)(wp + 8);
                ulonglong2 p67 = *(const ulonglong2*)(wp + 12);
                unsigned long long p8 = *(const unsigned long long*)(wp + 16);
                ffma2(acc[0], xv, p01.x);
                ffma2(acc[1], xv, p01.y);
                ffma2(acc[2], xv, p23.x);
                ffma2(acc[3], xv, p23.y);
                ffma2(acc[4], xv, p45.x);
                ffma2(acc[5], xv, p45.y);
                ffma2(acc[6], xv, p67.x);
                ffma2(acc[7], xv, p67.y);
                ffma2(acc[8], xv, p8);
            }
        }
    }
    int h = 2*h2 + rsel;
    float* dst = &g_offs[((size_t)((b*HH + h)*WW + w))*18];
#pragma unroll
    for (int p = 0; p < 9; p++) {
        float2 r = unpack2(acc[p]);
        dst[2*p]   = r.x;
        dst[2*p+1] = r.y;
    }
}

// ============ kernel 3.5: bilinear precompute ============
__global__ void k_precomp() {
    int idx = blockIdx.x*blockDim.x + threadIdx.x;
    if (idx >= PIX*K2) return;
    int pix = idx / K2, k = idx - pix*K2;
    int hw = pix & (HW-1);
    int h = hw >> 7, w = hw & 127;
    float dy = g_offs[pix*18 + 2*k];
    float dx = g_offs[pix*18 + 2*k + 1];
    int ky = k / 3, kx = k - ky*3;
    float py = (float)(h + ky - 1) + dy;
    float px = (float)(w + kx - 1) + dx;
    float y0f = floorf(py), x0f = floorf(px);
    float wy = py - y0f, wx = px - x0f;
    int y0 = (int)y0f, x0 = (int)x0f;
    bool vy0 = (y0 >= 0) && (y0 < HH);
    bool vy1 = (y0 >= -1) && (y0 < HH-1);
    bool vx0 = (x0 >= 0) && (x0 < WW);
    bool vx1 = (x0 >= -1) && (x0 < WW-1);
    int iy0 = min(max(y0, 0), HH-1), iy1 = min(max(y0+1, 0), HH-1);
    int ix0 = min(max(x0, 0), WW-1), ix1 = min(max(x0+1, 0), WW-1);
    float4 wv;
    wv.x = (vy0 && vx0) ? (1.f-wy)*(1.f-wx) : 0.f;
    wv.y = (vy0 && vx1) ? (1.f-wy)*wx       : 0.f;
    wv.z = (vy1 && vx0) ? wy*(1.f-wx)       : 0.f;
    wv.w = (vy1 && vx1) ? wy*wx             : 0.f;
    int4 ov;
    ov.x = (iy0*WW + ix0)*CH*4;
    ov.y = (iy0*WW + ix1)*CH*4;
    ov.z = (iy1*WW + ix0)*CH*4;
    ov.w = (iy1*WW + ix1)*CH*4;
    g_pw[idx] = wv;
    g_po[idx] = ov;
}

// ============ kernel 4: deformable conv v7 (MLP-batched gather) ============
// Block: 256 threads = 8 warps, 128 pixels (one image row), 64 oc.
// pw/po held lane-parallel (lane j = pixel j), prefetched one position ahead
// during GEMM; gather issues corner loads in chunks of 8 pixels (32 LDG.64
// in flight) before consuming. No __syncthreads; warps fully decoupled.
#define SMA_HI 0
#define SMA_LO 16384
#define SMEM_DEF 32768

__global__ void __launch_bounds__(256)
k_deform(const float* __restrict__ b_dcn, float* __restrict__ out) {
    char* sm = smraw;
    uint32_t sb = smem_u32(sm);
    int t = threadIdx.x;
    int lane = t & 31, warp = t >> 5;   // warp in [0,8)
    int blk = blockIdx.x;               // b*128 + h
    int b = blk >> 7, h = blk & 127;
    int pix0 = blk * WW;
    const char* xc = (const char*)&g_xn[(size_t)b * (HW*CH)];
    int lb = lane*8;                    // channel byte offset (2 floats per lane)
    int l16 = lane & 15;

    float acc[8][4];
#pragma unroll
    for (int i = 0; i < 8; i++)
#pragma unroll
        for (int j = 0; j < 4; j++) acc[i][j] = 0.f;

    // ldmatrix A address components
    int ltile = lane >> 3, lrow = lane & 7;
    int a_r = (ltile & 1)*8 + lrow;            // 0..15
    int a_gr = warp*16 + a_r;                  // global A row
    int a_cpar = ltile >> 1;                   // 0/1: chunk parity in k16
    uint32_t a_base = sb + a_gr*128;

    // lane-parallel pw/po: lane j (mod 16) holds pixel (warp*16+j)'s data
    size_t pp = (size_t)(pix0 + warp*16 + l16)*K2;
    float4 pw_r = g_pw[pp];             // position k=0
    int4   po_r = g_po[pp];

    for (int k = 0; k < K2; k++) {
        // ---- gather 16 warp-local pixels, 2 chunks of 8 (batched corner MLP) ----
#pragma unroll
        for (int ch_ = 0; ch_ < 2; ch_++) {
            float2 c00[8], c01[8], c10[8], c11[8];
#pragma unroll
            for (int jj = 0; jj < 8; jj++) {
                int j = ch_*8 + jj;
                int o0 = __shfl_sync(0xffffffffu, po_r.x, j);
                int o1 = __shfl_sync(0xffffffffu, po_r.y, j);
                int o2 = __shfl_sync(0xffffffffu, po_r.z, j);
                int o3 = __shfl_sync(0xffffffffu, po_r.w, j);
                c00[jj] = *(const float2*)(xc + o0 + lb);
                c01[jj] = *(const float2*)(xc + o1 + lb);
                c10[jj] = *(const float2*)(xc + o2 + lb);
                c11[jj] = *(const float2*)(xc + o3 + lb);
            }
#pragma unroll
            for (int jj = 0; jj < 8; jj++) {
                int j = ch_*8 + jj;
                float wx_ = __shfl_sync(0xffffffffu, pw_r.x, j);
                float wy_ = __shfl_sync(0xffffffffu, pw_r.y, j);
                float wz_ = __shfl_sync(0xffffffffu, pw_r.z, j);
                float ww_ = __shfl_sync(0xffffffffu, pw_r.w, j);
                float r0 = wx_*c00[jj].x + wy_*c01[jj].x + wz_*c10[jj].x + ww_*c11[jj].x;
                float r1 = wx_*c00[jj].y + wy_*c01[jj].y + wz_*c10[jj].y + ww_*c11[jj].y;
                unsigned h2 = pk_bf16x2(r0, r1);
                float h0 = __uint_as_float(h2 << 16);
                float h1 = __uint_as_float(h2 & 0xFFFF0000u);
                unsigned l2 = pk_bf16x2(r0 - h0, r1 - h1);
                unsigned off = (warp*16 + j)*128 + ((((lane >> 2) ^ jj) << 4) | ((lane & 3) << 2));
                *(unsigned*)(sm + SMA_HI + off) = h2;
                *(unsigned*)(sm + SMA_LO + off) = l2;
            }
        }
        __syncwarp();

        // prefetch next position's pw/po (covered by GEMM below)
        if (k < K2-1) {
            pw_r = g_pw[pp + k + 1];
            po_r = g_po[pp + k + 1];
        }

        // ---- GEMM: m16 x n64 x k64, 3-term bf16 split ----
        const uint4* bfH = &g_wfragH[k*512 + lane];
        const uint4* bfL = &g_wfragL[k*512 + lane];
#pragma unroll
        for (int kt = 0; kt < 4; kt++) {
            uint32_t aH[4], aL[4];
            int chunkk = 2*kt + a_cpar;
            uint32_t addr = a_base + ((chunkk ^ (a_gr & 7)) << 4);
            ldsm4(aH, addr + SMA_HI);
            ldsm4(aL, addr + SMA_LO);
#pragma unroll
            for (int ng = 0; ng < 4; ng++) {
                uint4 BH = bfH[(kt*4 + ng)*32];
                uint4 BL = bfL[(kt*4 + ng)*32];
                mma16816(acc[2*ng],   aH, BH.x, BH.y);
                mma16816(acc[2*ng],   aL, BH.x, BH.y);
                mma16816(acc[2*ng],   aH, BL.x, BL.y);
                mma16816(acc[2*ng+1], aH, BH.z, BH.w);
                mma16816(acc[2*ng+1], aL, BH.z, BH.w);
                mma16816(acc[2*ng+1], aH, BL.z, BL.w);
            }
        }
        __syncwarp();                   // all lanes done with A before overwrite
    }

    // epilogue: write fragments to NCHW out
    int r0 = lane >> 2;                 // 0..7
    int cq = (lane & 3)*2;
    int w0 = warp*16 + r0;
    size_t obase = (size_t)b*OC*HW + (size_t)h*WW;
#pragma unroll
    for (int nt = 0; nt < 8; nt++) {
        int oc = nt*8 + cq;
        float bias0 = b_dcn[oc];
        float bias1 = b_dcn[oc+1];
        float* o0 = &out[obase + (size_t)oc*HW];
        float* o1 = &out[obase + (size_t)(oc+1)*HW];
        o0[w0]     = acc[nt][0] + bias0;
        o1[w0]     = acc[nt][1] + bias1;
        o0[w0 + 8] = acc[nt][2] + bias0;
        o1[w0 + 8] = acc[nt][3] + bias1;
    }
}

// ============ launch ============
extern "C" void kernel_launch(void* const* d_in, const int* in_sizes, int n_in,
                              void* d_out, int out_size) {
    const float* x     = (const float*)d_in[0];
    const float* w_off = (const float*)d_in[1];
    const float* b_off = (const float*)d_in[2];
    const float* w_dcn = (const float*)d_in[3];
    const float* b_dcn = (const float*)d_in[4];
    float* out = (float*)d_out;

    const int SMEM_OFF = (4*SXROW + K2*CH*20) * 4;         // 179200 B
    cudaFuncSetAttribute(k_offconv, cudaFuncAttributeMaxDynamicSharedMemorySize, SMEM_OFF);
    cudaFuncSetAttribute(k_deform,  cudaFuncAttributeMaxDynamicSharedMemorySize, SMEM_DEF);

    k_transpose<<<dim3(WW/32, CH/32, BATCH*HH), dim3(32,8)>>>(x);
    k_reorder<<<64, 256>>>(w_off, w_dcn);
    k_offconv<<<BATCH*HH/2, 256, SMEM_OFF>>>(b_off);
    k_precomp<<<(PIX*K2 + 255)/256, 256>>>();
    k_deform<<<BATCH*HH, 256, SMEM_DEF>>>(b_dcn, out);
}

// round 9
// speedup vs baseline: 2.3635x; 1.1960x over previous
#include <cuda_runtime.h>
#include <cuda_bf16.h>
#include <math.h>
#include <stdint.h>

#define BATCH 4
#define CH 64
#define OC 64
#define HH 128
#define WW 128
#define HW (HH*WW)
#define PIX (BATCH*HW)
#define K2 9
#define KKD 576            // K2*CH

// -------- device scratch (no allocations allowed) --------
__device__ float g_xn[PIX*CH];            // x in NHWC fp32: [b][h][w][c]
__device__ unsigned g_xbf_hi[PIX*32];     // x bf16 hi plane: [pix][cpair]
__device__ unsigned g_xbf_lo[PIX*32];     // x bf16 lo plane
__device__ float g_offs[PIX*18];          // offsets: [pix][18]
__device__ uint4 g_wfragH[K2*512];        // deform B hi frags: [k][kt*4+ng][lane]
__device__ uint4 g_wfragL[K2*512];        // deform B lo frags
__device__ uint2 g_wofH[K2*384];          // offconv B hi frags: [k][kt*3+ng][lane]
__device__ uint2 g_wofL[K2*384];          // offconv B lo frags
__device__ float4 g_pw[PIX*K2];           // bilinear weights (validity folded)
__device__ int4  g_po[PIX*K2];            // per-corner clamped byte offsets

// single dynamic-shared symbol shared by all kernels
extern __shared__ char smraw[];

// pack two fp32 -> bf16x2 (first arg -> lower 16 bits)
__device__ __forceinline__ unsigned pk_bf16x2(float lo, float hi) {
    unsigned r;
    asm("cvt.rn.bf16x2.f32 %0, %1, %2;" : "=r"(r) : "f"(hi), "f"(lo));
    return r;
}
__device__ __forceinline__ uint32_t smem_u32(const void* p) {
    uint32_t a;
    asm("{ .reg .u64 t; cvta.to.shared.u64 t, %1; cvt.u32.u64 %0, t; }" : "=r"(a) : "l"(p));
    return a;
}
__device__ __forceinline__ void ldsm4(uint32_t* r, uint32_t addr) {
    asm volatile("ldmatrix.sync.aligned.m8n8.x4.shared.b16 {%0,%1,%2,%3}, [%4];"
        : "=r"(r[0]), "=r"(r[1]), "=r"(r[2]), "=r"(r[3]) : "r"(addr));
}
__device__ __forceinline__ void mma16816(float* c, const uint32_t* a, uint32_t b0, uint32_t b1) {
    asm volatile("mma.sync.aligned.m16n8k16.row.col.f32.bf16.bf16.f32 "
        "{%0,%1,%2,%3}, {%4,%5,%6,%7}, {%8,%9}, {%0,%1,%2,%3};"
        : "+f"(c[0]), "+f"(c[1]), "+f"(c[2]), "+f"(c[3])
        : "r"(a[0]), "r"(a[1]), "r"(a[2]), "r"(a[3]), "r"(b0), "r"(b1));
}

// ============ kernel 1: NCHW -> NHWC transpose + bf16 hi/lo planes ============
__global__ void k_transpose(const float* __restrict__ x) {
    __shared__ float tile[32][33];
    int bh = blockIdx.z;                 // b*128 + h
    int c0 = blockIdx.y * 32;
    int w0 = blockIdx.x * 32;
    int b = bh >> 7, h = bh & 127;
    int tx = threadIdx.x, ty = threadIdx.y;
#pragma unroll
    for (int i = 0; i < 4; i++) {
        int c = c0 + ty + i*8;
        tile[ty + i*8][tx] = x[((b*CH + c)*HH + h)*WW + w0 + tx];
    }
    __syncthreads();
#pragma unroll
    for (int i = 0; i < 4; i++) {
        int w = w0 + ty + i*8;
        g_xn[(bh*WW + w)*CH + c0 + tx] = tile[tx][ty + i*8];
    }
    // bf16 hi/lo planes: threads tx<16 write channel pair (c0+2tx, c0+2tx+1)
    if (tx < 16) {
#pragma unroll
        for (int i = 0; i < 4; i++) {
            int wi = ty + i*8;
            int w = w0 + wi;
            float v0 = tile[2*tx][wi];
            float v1 = tile[2*tx + 1][wi];
            unsigned h2 = pk_bf16x2(v0, v1);
            float h0 = __uint_as_float(h2 << 16);
            float h1 = __uint_as_float(h2 & 0xFFFF0000u);
            unsigned l2 = pk_bf16x2(v0 - h0, v1 - h1);
            int idx = (bh*WW + w)*32 + (c0 >> 1) + tx;
            g_xbf_hi[idx] = h2;
            g_xbf_lo[idx] = l2;
        }
    }
}

// ============ kernel 2: weight reorder -> fragment tables ============
__global__ void k_reorder(const float* __restrict__ w_off, const float* __restrict__ w_dcn) {
    int t = blockIdx.x*blockDim.x + threadIdx.x;
    int stride = gridDim.x*blockDim.x;
    unsigned hw_, lw_;
    float a0, a1, h0, h1;
#define MKW(SRC, KK, NN, KP, HRES, LRES) \
    a0 = SRC[(NN)*KKD + (KK)*K2 + KP]; \
    a1 = SRC[(NN)*KKD + (KK+1)*K2 + KP]; \
    hw_ = pk_bf16x2(a0, a1); \
    h0 = __uint_as_float(hw_ << 16); \
    h1 = __uint_as_float(hw_ & 0xFFFF0000u); \
    lw_ = pk_bf16x2(a0 - h0, a1 - h1); \
    HRES = hw_; LRES = lw_;

    // deform weight fragments (n64): [k][kt*4+ng][lane]
    for (int idx = t; idx < K2*512; idx += stride) {
        int kpos = idx / 512;
        int rem = idx & 511;
        int tile = rem >> 5;        // kt*4 + ng
        int lane = rem & 31;
        int kt = tile >> 2, ng = tile & 3;
        int n0 = ng*16 + (lane >> 2);
        int k0 = kt*16 + (lane & 3)*2;
        uint4 hi, lo;
        MKW(w_dcn, k0,     n0,     kpos, hi.x, lo.x)
        MKW(w_dcn, k0 + 8, n0,     kpos, hi.y, lo.y)
        MKW(w_dcn, k0,     n0 + 8, kpos, hi.z, lo.z)
        MKW(w_dcn, k0 + 8, n0 + 8, kpos, hi.w, lo.w)
        g_wfragH[idx] = hi;
        g_wfragL[idx] = lo;
    }
    // offconv weight fragments (n24, 18 valid): [k][kt*3+ng][lane]
    for (int idx = t; idx < K2*384; idx += stride) {
        int kpos = idx / 384;
        int rem = idx - kpos*384;
        int tile = rem >> 5;        // kt*3 + ng
        int lane = rem & 31;
        int kt = tile / 3, ng = tile - kt*3;
        int n0 = ng*8 + (lane >> 2);
        int k0 = kt*16 + (lane & 3)*2;
        uint2 hi, lo;
        if (n0 < 18) {
            MKW(w_off, k0,     n0, kpos, hi.x, lo.x)
            MKW(w_off, k0 + 8, n0, kpos, hi.y, lo.y)
        } else {
            hi.x = hi.y = lo.x = lo.y = 0u;
        }
        g_wofH[idx] = hi;
        g_wofL[idx] = lo;
    }
#undef MKW
}

// ============ kernel 3: offset conv via mma.sync (C=64 -> 18, 3x3, pad1) ============
// Block: 256 threads = 8 warps, one image row (128 px). Per position: stage A
// (128x64 bf16 hi/lo, from pre-split planes, predicated borders), then each
// warp does m16 x n24 x k64 with 3-term split. Warp-private A -> syncwarp only.
#define OSA_HI 0
#define OSA_LO 16384
#define SMEM_OFF 32768

__global__ void __launch_bounds__(256)
k_offconv(const float* __restrict__ b_off) {
    char* sm = smraw;
    uint32_t sb = smem_u32(sm);
    int t = threadIdx.x;
    int lane = t & 31, warp = t >> 5;
    int blk = blockIdx.x;               // b*128 + h
    int b = blk >> 7, h = blk & 127;
    int pix0 = blk * WW;

    float acc[3][4];
#pragma unroll
    for (int i = 0; i < 3; i++)
#pragma unroll
        for (int j = 0; j < 4; j++) acc[i][j] = 0.f;

    int ltile = lane >> 3, lrow = lane & 7;
    int a_r = (ltile & 1)*8 + lrow;
    int a_gr = warp*16 + a_r;
    int a_cpar = ltile >> 1;
    uint32_t a_base = sb + a_gr*128;

    for (int k = 0; k < K2; k++) {
        int ky = k / 3, kx = k - ky*3;
        int y = h + ky - 1;
        bool vy = (unsigned)y < HH;
        const unsigned* hp = &g_xbf_hi[((size_t)(b*HH + (vy ? y : 0)))*WW*32];
        const unsigned* lp = &g_xbf_lo[((size_t)(b*HH + (vy ? y : 0)))*WW*32];
#pragma unroll 8
        for (int j = 0; j < 16; j++) {
            int p = warp*16 + j;
            int xx = p + kx - 1;
            bool v = vy && ((unsigned)xx < WW);
            unsigned h2 = v ? hp[xx*32 + lane] : 0u;
            unsigned l2 = v ? lp[xx*32 + lane] : 0u;
            unsigned off = p*128 + ((((lane >> 2) ^ (j & 7)) << 4) | ((lane & 3) << 2));
            *(unsigned*)(sm + OSA_HI + off) = h2;
            *(unsigned*)(sm + OSA_LO + off) = l2;
        }
        __syncwarp();

        const uint2* bfH = &g_wofH[k*384 + lane];
        const uint2* bfL = &g_wofL[k*384 + lane];
#pragma unroll
        for (int kt = 0; kt < 4; kt++) {
            uint32_t aH[4], aL[4];
            int chunkk = 2*kt + a_cpar;
            uint32_t addr = a_base + ((chunkk ^ (a_gr & 7)) << 4);
            ldsm4(aH, addr + OSA_HI);
            ldsm4(aL, addr + OSA_LO);
#pragma unroll
            for (int ng = 0; ng < 3; ng++) {
                uint2 BH = bfH[(kt*3 + ng)*32];
                uint2 BL = bfL[(kt*3 + ng)*32];
                mma16816(acc[ng], aH, BH.x, BH.y);
                mma16816(acc[ng], aL, BH.x, BH.y);
                mma16816(acc[ng], aH, BL.x, BL.y);
            }
        }
        __syncwarp();
    }

    // epilogue: D rows = pixels, cols = offset channel (first 18 valid)
    int r0 = lane >> 2;
    int cq = (lane & 3)*2;
    int p0 = pix0 + warp*16 + r0;
    int p1 = p0 + 8;
#pragma unroll
    for (int ng = 0; ng < 3; ng++) {
        int col = ng*8 + cq;
        if (col < 18) {
            float bi0 = b_off[col], bi1 = b_off[col+1];
            g_offs[(size_t)p0*18 + col]     = acc[ng][0] + bi0;
            g_offs[(size_t)p0*18 + col + 1] = acc[ng][1] + bi1;
            g_offs[(size_t)p1*18 + col]     = acc[ng][2] + bi0;
            g_offs[(size_t)p1*18 + col + 1] = acc[ng][3] + bi1;
        }
    }
}

// ============ kernel 3.5: bilinear precompute ============
__global__ void k_precomp() {
    int idx = blockIdx.x*blockDim.x + threadIdx.x;
    if (idx >= PIX*K2) return;
    int pix = idx / K2, k = idx - pix*K2;
    int hw = pix & (HW-1);
    int h = hw >> 7, w = hw & 127;
    float dy = g_offs[pix*18 + 2*k];
    float dx = g_offs[pix*18 + 2*k + 1];
    int ky = k / 3, kx = k - ky*3;
    float py = (float)(h + ky - 1) + dy;
    float px = (float)(w + kx - 1) + dx;
    float y0f = floorf(py), x0f = floorf(px);
    float wy = py - y0f, wx = px - x0f;
    int y0 = (int)y0f, x0 = (int)x0f;
    bool vy0 = (y0 >= 0) && (y0 < HH);
    bool vy1 = (y0 >= -1) && (y0 < HH-1);
    bool vx0 = (x0 >= 0) && (x0 < WW);
    bool vx1 = (x0 >= -1) && (x0 < WW-1);
    int iy0 = min(max(y0, 0), HH-1), iy1 = min(max(y0+1, 0), HH-1);
    int ix0 = min(max(x0, 0), WW-1), ix1 = min(max(x0+1, 0), WW-1);
    float4 wv;
    wv.x = (vy0 && vx0) ? (1.f-wy)*(1.f-wx) : 0.f;
    wv.y = (vy0 && vx1) ? (1.f-wy)*wx       : 0.f;
    wv.z = (vy1 && vx0) ? wy*(1.f-wx)       : 0.f;
    wv.w = (vy1 && vx1) ? wy*wx             : 0.f;
    int4 ov;
    ov.x = (iy0*WW + ix0)*CH*4;
    ov.y = (iy0*WW + ix1)*CH*4;
    ov.z = (iy1*WW + ix0)*CH*4;
    ov.w = (iy1*WW + ix1)*CH*4;
    g_pw[idx] = wv;
    g_po[idx] = ov;
}

// ============ kernel 4: deformable conv v8 (128-thread blocks) ============
// Block: 128 threads = 4 warps, 64 pixels, 64 oc. Same per-warp structure as
// v7 (lane-parallel pw/po, chunked corner MLP, B frags from gmem); halved
// block size raises CTAs/SM (reg-limited) -> more warps to hide gather latency.
#define SMA_HI 0
#define SMA_LO 8192
#define SMEM_DEF 16384

__global__ void __launch_bounds__(128)
k_deform(const float* __restrict__ b_dcn, float* __restrict__ out) {
    char* sm = smraw;
    uint32_t sb = smem_u32(sm);
    int t = threadIdx.x;
    int lane = t & 31, warp = t >> 5;   // warp in [0,4)
    int blk = blockIdx.x;               // 0..1023
    int pix0 = blk * 64;
    int b = pix0 >> 14;
    int h = (pix0 & (HW-1)) >> 7;
    const char* xc = (const char*)&g_xn[(size_t)b * (HW*CH)];
    int lb = lane*8;                    // channel byte offset (2 floats per lane)
    int l16 = lane & 15;

    float acc[8][4];
#pragma unroll
    for (int i = 0; i < 8; i++)
#pragma unroll
        for (int j = 0; j < 4; j++) acc[i][j] = 0.f;

    int ltile = lane >> 3, lrow = lane & 7;
    int a_r = (ltile & 1)*8 + lrow;
    int a_gr = warp*16 + a_r;           // local A row (0..63)
    int a_cpar = ltile >> 1;
    uint32_t a_base = sb + a_gr*128;

    size_t pp = (size_t)(pix0 + warp*16 + l16)*K2;
    float4 pw_r = g_pw[pp];
    int4   po_r = g_po[pp];

    for (int k = 0; k < K2; k++) {
#pragma unroll
        for (int ch_ = 0; ch_ < 2; ch_++) {
            float2 c00[8], c01[8], c10[8], c11[8];
#pragma unroll
            for (int jj = 0; jj < 8; jj++) {
                int j = ch_*8 + jj;
                int o0 = __shfl_sync(0xffffffffu, po_r.x, j);
                int o1 = __shfl_sync(0xffffffffu, po_r.y, j);
                int o2 = __shfl_sync(0xffffffffu, po_r.z, j);
                int o3 = __shfl_sync(0xffffffffu, po_r.w, j);
                c00[jj] = *(const float2*)(xc + o0 + lb);
                c01[jj] = *(const float2*)(xc + o1 + lb);
                c10[jj] = *(const float2*)(xc + o2 + lb);
                c11[jj] = *(const float2*)(xc + o3 + lb);
            }
#pragma unroll
            for (int jj = 0; jj < 8; jj++) {
                int j = ch_*8 + jj;
                float wx_ = __shfl_sync(0xffffffffu, pw_r.x, j);
                float wy_ = __shfl_sync(0xffffffffu, pw_r.y, j);
                float wz_ = __shfl_sync(0xffffffffu, pw_r.z, j);
                float ww_ = __shfl_sync(0xffffffffu, pw_r.w, j);
                float r0 = wx_*c00[jj].x + wy_*c01[jj].x + wz_*c10[jj].x + ww_*c11[jj].x;
                float r1 = wx_*c00[jj].y + wy_*c01[jj].y + wz_*c10[jj].y + ww_*c11[jj].y;
                unsigned h2 = pk_bf16x2(r0, r1);
                float h0 = __uint_as_float(h2 << 16);
                float h1 = __uint_as_float(h2 & 0xFFFF0000u);
                unsigned l2 = pk_bf16x2(r0 - h0, r1 - h1);
                unsigned off = (warp*16 + j)*128 + ((((lane >> 2) ^ jj) << 4) | ((lane & 3) << 2));
                *(unsigned*)(sm + SMA_HI + off) = h2;
                *(unsigned*)(sm + SMA_LO + off) = l2;
            }
        }
        __syncwarp();

        if (k < K2-1) {
            pw_r = g_pw[pp + k + 1];
            po_r = g_po[pp + k + 1];
        }

        const uint4* bfH = &g_wfragH[k*512 + lane];
        const uint4* bfL = &g_wfragL[k*512 + lane];
#pragma unroll
        for (int kt = 0; kt < 4; kt++) {
            uint32_t aH[4], aL[4];
            int chunkk = 2*kt + a_cpar;
            uint32_t addr = a_base + ((chunkk ^ (a_gr & 7)) << 4);
            ldsm4(aH, addr + SMA_HI);
            ldsm4(aL, addr + SMA_LO);
#pragma unroll
            for (int ng = 0; ng < 4; ng++) {
                uint4 BH = bfH[(kt*4 + ng)*32];
                uint4 BL = bfL[(kt*4 + ng)*32];
                mma16816(acc[2*ng],   aH, BH.x, BH.y);
                mma16816(acc[2*ng],   aL, BH.x, BH.y);
                mma16816(acc[2*ng],   aH, BL.x, BL.y);
                mma16816(acc[2*ng+1], aH, BH.z, BH.w);
                mma16816(acc[2*ng+1], aL, BH.z, BH.w);
                mma16816(acc[2*ng+1], aH, BL.z, BL.w);
            }
        }
        __syncwarp();
    }

    // epilogue: write fragments to NCHW out
    int r0 = lane >> 2;
    int cq = (lane & 3)*2;
    int w0 = (pix0 & 127) + warp*16 + r0;
    size_t obase = (size_t)b*OC*HW + (size_t)h*WW;
#pragma unroll
    for (int nt = 0; nt < 8; nt++) {
        int oc = nt*8 + cq;
        float bias0 = b_dcn[oc];
        float bias1 = b_dcn[oc+1];
        float* o0 = &out[obase + (size_t)oc*HW];
        float* o1 = &out[obase + (size_t)(oc+1)*HW];
        o0[w0]     = acc[nt][0] + bias0;
        o1[w0]     = acc[nt][1] + bias1;
        o0[w0 + 8] = acc[nt][2] + bias0;
        o1[w0 + 8] = acc[nt][3] + bias1;
    }
}

// ============ launch ============
extern "C" void kernel_launch(void* const* d_in, const int* in_sizes, int n_in,
                              void* d_out, int out_size) {
    const float* x     = (const float*)d_in[0];
    const float* w_off = (const float*)d_in[1];
    const float* b_off = (const float*)d_in[2];
    const float* w_dcn = (const float*)d_in[3];
    const float* b_dcn = (const float*)d_in[4];
    float* out = (float*)d_out;

    cudaFuncSetAttribute(k_offconv, cudaFuncAttributeMaxDynamicSharedMemorySize, SMEM_OFF);
    cudaFuncSetAttribute(k_deform,  cudaFuncAttributeMaxDynamicSharedMemorySize, SMEM_DEF);

    k_transpose<<<dim3(WW/32, CH/32, BATCH*HH), dim3(32,8)>>>(x);
    k_reorder<<<64, 256>>>(w_off, w_dcn);
    k_offconv<<<BATCH*HH, 256, SMEM_OFF>>>(b_off);
    k_precomp<<<(PIX*K2 + 255)/256, 256>>>();
    k_deform<<<PIX/64, 128, SMEM_DEF>>>(b_dcn, out);
}

// round 10
// speedup vs baseline: 2.4617x; 1.0415x over previous
#include <cuda_runtime.h>
#include <cuda_bf16.h>
#include <math.h>
#include <stdint.h>

#define BATCH 4
#define CH 64
#define OC 64
#define HH 128
#define WW 128
#define HW (HH*WW)
#define PIX (BATCH*HW)
#define K2 9
#define KKD 576            // K2*CH

// -------- device scratch (no allocations allowed) --------
__device__ float g_xn[PIX*CH];            // x in NHWC fp32: [b][h][w][c]
__device__ unsigned g_xbf_hi[PIX*32];     // x bf16 hi plane: [pix][cpair]
__device__ unsigned g_xbf_lo[PIX*32];     // x bf16 lo plane
__device__ float g_offs[PIX*18];          // offsets: [pix][18]
__device__ uint4 g_wfragH[K2*512];        // deform B hi frags: [k][kt*4+ng][lane]
__device__ uint4 g_wfragL[K2*512];        // deform B lo frags
__device__ uint2 g_wofH[K2*384];          // offconv B hi frags: [k][kt*3+ng][lane]
__device__ uint2 g_wofL[K2*384];          // offconv B lo frags
__device__ float4 g_pw[PIX*K2];           // bilinear weights (validity folded)
__device__ int4  g_po[PIX*K2];            // per-corner clamped byte offsets

// single dynamic-shared symbol shared by all kernels
extern __shared__ char smraw[];

// pack two fp32 -> bf16x2 (first arg -> lower 16 bits)
__device__ __forceinline__ unsigned pk_bf16x2(float lo, float hi) {
    unsigned r;
    asm("cvt.rn.bf16x2.f32 %0, %1, %2;" : "=r"(r) : "f"(hi), "f"(lo));
    return r;
}
__device__ __forceinline__ uint32_t smem_u32(const void* p) {
    uint32_t a;
    asm("{ .reg .u64 t; cvta.to.shared.u64 t, %1; cvt.u32.u64 %0, t; }" : "=r"(a) : "l"(p));
    return a;
}
__device__ __forceinline__ void ldsm4(uint32_t* r, uint32_t addr) {
    asm volatile("ldmatrix.sync.aligned.m8n8.x4.shared.b16 {%0,%1,%2,%3}, [%4];"
        : "=r"(r[0]), "=r"(r[1]), "=r"(r[2]), "=r"(r[3]) : "r"(addr));
}
__device__ __forceinline__ void mma16816(float* c, const uint32_t* a, uint32_t b0, uint32_t b1) {
    asm volatile("mma.sync.aligned.m16n8k16.row.col.f32.bf16.bf16.f32 "
        "{%0,%1,%2,%3}, {%4,%5,%6,%7}, {%8,%9}, {%0,%1,%2,%3};"
        : "+f"(c[0]), "+f"(c[1]), "+f"(c[2]), "+f"(c[3])
        : "r"(a[0]), "r"(a[1]), "r"(a[2]), "r"(a[3]), "r"(b0), "r"(b1));
}

// ============ kernel 1: NCHW -> NHWC transpose + bf16 hi/lo planes ============
__global__ void k_transpose(const float* __restrict__ x) {
    __shared__ float tile[32][33];
    int bh = blockIdx.z;                 // b*128 + h
    int c0 = blockIdx.y * 32;
    int w0 = blockIdx.x * 32;
    int b = bh >> 7, h = bh & 127;
    int tx = threadIdx.x, ty = threadIdx.y;
#pragma unroll
    for (int i = 0; i < 4; i++) {
        int c = c0 + ty + i*8;
        tile[ty + i*8][tx] = x[((b*CH + c)*HH + h)*WW + w0 + tx];
    }
    __syncthreads();
#pragma unroll
    for (int i = 0; i < 4; i++) {
        int w = w0 + ty + i*8;
        g_xn[(bh*WW + w)*CH + c0 + tx] = tile[tx][ty + i*8];
    }
    // bf16 hi/lo planes: threads tx<16 write channel pair (c0+2tx, c0+2tx+1)
    if (tx < 16) {
#pragma unroll
        for (int i = 0; i < 4; i++) {
            int wi = ty + i*8;
            int w = w0 + wi;
            float v0 = tile[2*tx][wi];
            float v1 = tile[2*tx + 1][wi];
            unsigned h2 = pk_bf16x2(v0, v1);
            float h0 = __uint_as_float(h2 << 16);
            float h1 = __uint_as_float(h2 & 0xFFFF0000u);
            unsigned l2 = pk_bf16x2(v0 - h0, v1 - h1);
            int idx = (bh*WW + w)*32 + (c0 >> 1) + tx;
            g_xbf_hi[idx] = h2;
            g_xbf_lo[idx] = l2;
        }
    }
}

// ============ kernel 2: weight reorder -> fragment tables ============
__global__ void k_reorder(const float* __restrict__ w_off, const float* __restrict__ w_dcn) {
    int t = blockIdx.x*blockDim.x + threadIdx.x;
    int stride = gridDim.x*blockDim.x;
    unsigned hw_, lw_;
    float a0, a1, h0, h1;
#define MKW(SRC, KK, NN, KP, HRES, LRES) \
    a0 = SRC[(NN)*KKD + (KK)*K2 + KP]; \
    a1 = SRC[(NN)*KKD + (KK+1)*K2 + KP]; \
    hw_ = pk_bf16x2(a0, a1); \
    h0 = __uint_as_float(hw_ << 16); \
    h1 = __uint_as_float(hw_ & 0xFFFF0000u); \
    lw_ = pk_bf16x2(a0 - h0, a1 - h1); \
    HRES = hw_; LRES = lw_;

    for (int idx = t; idx < K2*512; idx += stride) {
        int kpos = idx / 512;
        int rem = idx & 511;
        int tile = rem >> 5;        // kt*4 + ng
        int lane = rem & 31;
        int kt = tile >> 2, ng = tile & 3;
        int n0 = ng*16 + (lane >> 2);
        int k0 = kt*16 + (lane & 3)*2;
        uint4 hi, lo;
        MKW(w_dcn, k0,     n0,     kpos, hi.x, lo.x)
        MKW(w_dcn, k0 + 8, n0,     kpos, hi.y, lo.y)
        MKW(w_dcn, k0,     n0 + 8, kpos, hi.z, lo.z)
        MKW(w_dcn, k0 + 8, n0 + 8, kpos, hi.w, lo.w)
        g_wfragH[idx] = hi;
        g_wfragL[idx] = lo;
    }
    for (int idx = t; idx < K2*384; idx += stride) {
        int kpos = idx / 384;
        int rem = idx - kpos*384;
        int tile = rem >> 5;        // kt*3 + ng
        int lane = rem & 31;
        int kt = tile / 3, ng = tile - kt*3;
        int n0 = ng*8 + (lane >> 2);
        int k0 = kt*16 + (lane & 3)*2;
        uint2 hi, lo;
        if (n0 < 18) {
            MKW(w_off, k0,     n0, kpos, hi.x, lo.x)
            MKW(w_off, k0 + 8, n0, kpos, hi.y, lo.y)
        } else {
            hi.x = hi.y = lo.x = lo.y = 0u;
        }
        g_wofH[idx] = hi;
        g_wofL[idx] = lo;
    }
#undef MKW
}

// ============ kernel 3: offset conv via mma.sync (C=64 -> 18, 3x3, pad1) ============
#define OSA_HI 0
#define OSA_LO 16384
#define SMEM_OFF 32768

__global__ void __launch_bounds__(256)
k_offconv(const float* __restrict__ b_off) {
    char* sm = smraw;
    uint32_t sb = smem_u32(sm);
    int t = threadIdx.x;
    int lane = t & 31, warp = t >> 5;
    int blk = blockIdx.x;               // b*128 + h
    int b = blk >> 7, h = blk & 127;
    int pix0 = blk * WW;

    float acc[3][4];
#pragma unroll
    for (int i = 0; i < 3; i++)
#pragma unroll
        for (int j = 0; j < 4; j++) acc[i][j] = 0.f;

    int ltile = lane >> 3, lrow = lane & 7;
    int a_r = (ltile & 1)*8 + lrow;
    int a_gr = warp*16 + a_r;
    int a_cpar = ltile >> 1;
    uint32_t a_base = sb + a_gr*128;

    for (int k = 0; k < K2; k++) {
        int ky = k / 3, kx = k - ky*3;
        int y = h + ky - 1;
        bool vy = (unsigned)y < HH;
        const unsigned* hp = &g_xbf_hi[((size_t)(b*HH + (vy ? y : 0)))*WW*32];
        const unsigned* lp = &g_xbf_lo[((size_t)(b*HH + (vy ? y : 0)))*WW*32];
#pragma unroll 8
        for (int j = 0; j < 16; j++) {
            int p = warp*16 + j;
            int xx = p + kx - 1;
            bool v = vy && ((unsigned)xx < WW);
            unsigned h2 = v ? hp[xx*32 + lane] : 0u;
            unsigned l2 = v ? lp[xx*32 + lane] : 0u;
            unsigned off = p*128 + ((((lane >> 2) ^ (j & 7)) << 4) | ((lane & 3) << 2));
            *(unsigned*)(sm + OSA_HI + off) = h2;
            *(unsigned*)(sm + OSA_LO + off) = l2;
        }
        __syncwarp();

        const uint2* bfH = &g_wofH[k*384 + lane];
        const uint2* bfL = &g_wofL[k*384 + lane];
#pragma unroll
        for (int kt = 0; kt < 4; kt++) {
            uint32_t aH[4], aL[4];
            int chunkk = 2*kt + a_cpar;
            uint32_t addr = a_base + ((chunkk ^ (a_gr & 7)) << 4);
            ldsm4(aH, addr + OSA_HI);
            ldsm4(aL, addr + OSA_LO);
#pragma unroll
            for (int ng = 0; ng < 3; ng++) {
                uint2 BH = bfH[(kt*3 + ng)*32];
                uint2 BL = bfL[(kt*3 + ng)*32];
                mma16816(acc[ng], aH, BH.x, BH.y);
                mma16816(acc[ng], aL, BH.x, BH.y);
                mma16816(acc[ng], aH, BL.x, BL.y);
            }
        }
        __syncwarp();
    }

    int r0 = lane >> 2;
    int cq = (lane & 3)*2;
    int p0 = pix0 + warp*16 + r0;
    int p1 = p0 + 8;
#pragma unroll
    for (int ng = 0; ng < 3; ng++) {
        int col = ng*8 + cq;
        if (col < 18) {
            float bi0 = b_off[col], bi1 = b_off[col+1];
            g_offs[(size_t)p0*18 + col]     = acc[ng][0] + bi0;
            g_offs[(size_t)p0*18 + col + 1] = acc[ng][1] + bi1;
            g_offs[(size_t)p1*18 + col]     = acc[ng][2] + bi0;
            g_offs[(size_t)p1*18 + col + 1] = acc[ng][3] + bi1;
        }
    }
}

// ============ kernel 3.5: bilinear precompute ============
__global__ void k_precomp() {
    int idx = blockIdx.x*blockDim.x + threadIdx.x;
    if (idx >= PIX*K2) return;
    int pix = idx / K2, k = idx - pix*K2;
    int hw = pix & (HW-1);
    int h = hw >> 7, w = hw & 127;
    float dy = g_offs[pix*18 + 2*k];
    float dx = g_offs[pix*18 + 2*k + 1];
    int ky = k / 3, kx = k - ky*3;
    float py = (float)(h + ky - 1) + dy;
    float px = (float)(w + kx - 1) + dx;
    float y0f = floorf(py), x0f = floorf(px);
    float wy = py - y0f, wx = px - x0f;
    int y0 = (int)y0f, x0 = (int)x0f;
    bool vy0 = (y0 >= 0) && (y0 < HH);
    bool vy1 = (y0 >= -1) && (y0 < HH-1);
    bool vx0 = (x0 >= 0) && (x0 < WW);
    bool vx1 = (x0 >= -1) && (x0 < WW-1);
    int iy0 = min(max(y0, 0), HH-1), iy1 = min(max(y0+1, 0), HH-1);
    int ix0 = min(max(x0, 0), WW-1), ix1 = min(max(x0+1, 0), WW-1);
    float4 wv;
    wv.x = (vy0 && vx0) ? (1.f-wy)*(1.f-wx) : 0.f;
    wv.y = (vy0 && vx1) ? (1.f-wy)*wx       : 0.f;
    wv.z = (vy1 && vx0) ? wy*(1.f-wx)       : 0.f;
    wv.w = (vy1 && vx1) ? wy*wx             : 0.f;
    int4 ov;
    ov.x = (iy0*WW + ix0)*CH*4;
    ov.y = (iy0*WW + ix1)*CH*4;
    ov.z = (iy1*WW + ix0)*CH*4;
    ov.w = (iy1*WW + ix1)*CH*4;
    g_pw[idx] = wv;
    g_po[idx] = ov;
}

// ============ kernel 4: deformable conv v9 (2-pass gather, reg-capped) ============
// Block: 128 threads = 4 warps, 64 pixels, 64 oc. Gather per 8-px chunk in two
// corner passes (top then bottom) to cap live registers at ~48; launch_bounds
// (128,6) guarantees >=6 CTAs/SM (24 warps) for gather-latency coverage.
#define SMA_HI 0
#define SMA_LO 8192
#define SMEM_DEF 16384

__global__ void __launch_bounds__(128, 6)
k_deform(const float* __restrict__ b_dcn, float* __restrict__ out) {
    char* sm = smraw;
    uint32_t sb = smem_u32(sm);
    int t = threadIdx.x;
    int lane = t & 31, warp = t >> 5;   // warp in [0,4)
    int blk = blockIdx.x;               // 0..1023
    int pix0 = blk * 64;
    int b = pix0 >> 14;
    int h = (pix0 & (HW-1)) >> 7;
    const char* xc = (const char*)&g_xn[(size_t)b * (HW*CH)];
    int lb = lane*8;                    // channel byte offset (2 floats per lane)
    int l16 = lane & 15;

    float acc[8][4];
#pragma unroll
    for (int i = 0; i < 8; i++)
#pragma unroll
        for (int j = 0; j < 4; j++) acc[i][j] = 0.f;

    int ltile = lane >> 3, lrow = lane & 7;
    int a_r = (ltile & 1)*8 + lrow;
    int a_gr = warp*16 + a_r;           // local A row (0..63)
    int a_cpar = ltile >> 1;
    uint32_t a_base = sb + a_gr*128;

    size_t pp = (size_t)(pix0 + warp*16 + l16)*K2;
    float4 pw_r = g_pw[pp];
    int4   po_r = g_po[pp];

    for (int k = 0; k < K2; k++) {
#pragma unroll
        for (int ch_ = 0; ch_ < 2; ch_++) {
            float2 part[8];
            // pass 1: top corners c00/c01
            {
                float2 c00[8], c01[8];
#pragma unroll
                for (int jj = 0; jj < 8; jj++) {
                    int j = ch_*8 + jj;
                    int o0 = __shfl_sync(0xffffffffu, po_r.x, j);
                    int o1 = __shfl_sync(0xffffffffu, po_r.y, j);
                    c00[jj] = *(const float2*)(xc + o0 + lb);
                    c01[jj] = *(const float2*)(xc + o1 + lb);
                }
#pragma unroll
                for (int jj = 0; jj < 8; jj++) {
                    int j = ch_*8 + jj;
                    float w0_ = __shfl_sync(0xffffffffu, pw_r.x, j);
                    float w1_ = __shfl_sync(0xffffffffu, pw_r.y, j);
                    part[jj].x = w0_*c00[jj].x + w1_*c01[jj].x;
                    part[jj].y = w0_*c00[jj].y + w1_*c01[jj].y;
                }
            }
            // pass 2: bottom corners c10/c11 + finish + convert + store
            {
                float2 c10[8], c11[8];
#pragma unroll
                for (int jj = 0; jj < 8; jj++) {
                    int j = ch_*8 + jj;
                    int o2 = __shfl_sync(0xffffffffu, po_r.z, j);
                    int o3 = __shfl_sync(0xffffffffu, po_r.w, j);
                    c10[jj] = *(const float2*)(xc + o2 + lb);
                    c11[jj] = *(const float2*)(xc + o3 + lb);
                }
#pragma unroll
                for (int jj = 0; jj < 8; jj++) {
                    int j = ch_*8 + jj;
                    float w2_ = __shfl_sync(0xffffffffu, pw_r.z, j);
                    float w3_ = __shfl_sync(0xffffffffu, pw_r.w, j);
                    float r0 = part[jj].x + w2_*c10[jj].x + w3_*c11[jj].x;
                    float r1 = part[jj].y + w2_*c10[jj].y + w3_*c11[jj].y;
                    unsigned h2 = pk_bf16x2(r0, r1);
                    float h0 = __uint_as_float(h2 << 16);
                    float h1 = __uint_as_float(h2 & 0xFFFF0000u);
                    unsigned l2 = pk_bf16x2(r0 - h0, r1 - h1);
                    unsigned off = (warp*16 + j)*128 + ((((lane >> 2) ^ jj) << 4) | ((lane & 3) << 2));
                    *(unsigned*)(sm + SMA_HI + off) = h2;
                    *(unsigned*)(sm + SMA_LO + off) = l2;
                }
            }
        }
        __syncwarp();

        if (k < K2-1) {
            pw_r = g_pw[pp + k + 1];
            po_r = g_po[pp + k + 1];
        }

        const uint4* bfH = &g_wfragH[k*512 + lane];
        const uint4* bfL = &g_wfragL[k*512 + lane];
#pragma unroll
        for (int kt = 0; kt < 4; kt++) {
            uint32_t aH[4], aL[4];
            int chunkk = 2*kt + a_cpar;
            uint32_t addr = a_base + ((chunkk ^ (a_gr & 7)) << 4);
            ldsm4(aH, addr + SMA_HI);
            ldsm4(aL, addr + SMA_LO);
#pragma unroll
            for (int ng = 0; ng < 4; ng++) {
                uint4 BH = bfH[(kt*4 + ng)*32];
                uint4 BL = bfL[(kt*4 + ng)*32];
                mma16816(acc[2*ng],   aH, BH.x, BH.y);
                mma16816(acc[2*ng],   aL, BH.x, BH.y);
                mma16816(acc[2*ng],   aH, BL.x, BL.y);
                mma16816(acc[2*ng+1], aH, BH.z, BH.w);
                mma16816(acc[2*ng+1], aL, BH.z, BH.w);
                mma16816(acc[2*ng+1], aH, BL.z, BL.w);
            }
        }
        __syncwarp();
    }

    // epilogue: write fragments to NCHW out
    int r0 = lane >> 2;
    int cq = (lane & 3)*2;
    int w0 = (pix0 & 127) + warp*16 + r0;
    size_t obase = (size_t)b*OC*HW + (size_t)h*WW;
#pragma unroll
    for (int nt = 0; nt < 8; nt++) {
        int oc = nt*8 + cq;
        float bias0 = b_dcn[oc];
        float bias1 = b_dcn[oc+1];
        float* o0 = &out[obase + (size_t)oc*HW];
        float* o1 = &out[obase + (size_t)(oc+1)*HW];
        o0[w0]     = acc[nt][0] + bias0;
        o1[w0]     = acc[nt][1] + bias1;
        o0[w0 + 8] = acc[nt][2] + bias0;
        o1[w0 + 8] = acc[nt][3] + bias1;
    }
}

// ============ launch ============
extern "C" void kernel_launch(void* const* d_in, const int* in_sizes, int n_in,
                              void* d_out, int out_size) {
    const float* x     = (const float*)d_in[0];
    const float* w_off = (const float*)d_in[1];
    const float* b_off = (const float*)d_in[2];
    const float* w_dcn = (const float*)d_in[3];
    const float* b_dcn = (const float*)d_in[4];
    float* out = (float*)d_out;

    cudaFuncSetAttribute(k_offconv, cudaFuncAttributeMaxDynamicSharedMemorySize, SMEM_OFF);
    cudaFuncSetAttribute(k_deform,  cudaFuncAttributeMaxDynamicSharedMemorySize, SMEM_DEF);

    k_transpose<<<dim3(WW/32, CH/32, BATCH*HH), dim3(32,8)>>>(x);
    k_reorder<<<64, 256>>>(w_off, w_dcn);
    k_offconv<<<BATCH*HH, 256, SMEM_OFF>>>(b_off);
    k_precomp<<<(PIX*K2 + 255)/256, 256>>>();
    k_deform<<<PIX/64, 128, SMEM_DEF>>>(b_dcn, out);
}